// round 1
// baseline (speedup 1.0000x reference)
#include <cuda_runtime.h>
#include <math.h>

// ---------------- problem constants ----------------
#define BB      64
#define NP      377
#define NROWS   (BB * NP)        // 24128  (divisible by 64: 24128/64 = 377)
#define CIN     384
#define HID     128
#define H2X     256              // 2*hid
#define SD      16
#define KNEI    6
#define PIN_DIM (SD * (KNEI + 1)) // 112
#define NSTEPS  16
#define FH      37               // feature H=W
#define DHH     518              // depth H=W

// ---------------- scratch (static device memory; no allocation) -------------
__device__ float g_Fs[(size_t)NROWS * CIN];     // sampled features
__device__ float g_dep[NROWS];                  // sampled depth
__device__ float g_bufA[(size_t)NROWS * H2X];   // 256-wide activations
__device__ float g_bufB[(size_t)NROWS * HID];   // 128-wide activations
__device__ float g_bufC[(size_t)NROWS * HID];   // 128-wide activations
__device__ float g_init[(size_t)NROWS * SD];
__device__ float g_state[(size_t)NROWS * SD];
__device__ float g_pin[(size_t)NROWS * PIN_DIM];
__device__ int   g_idx[(size_t)NROWS * KNEI];

// ---------------- bilinear sampling (features + depth) ----------------------
__global__ void sample_kernel(const float* __restrict__ feat,
                              const float* __restrict__ depth,
                              const float* __restrict__ sx,
                              const float* __restrict__ sy) {
    int row = blockIdx.x;
    int b = row / NP, n = row % NP;
    float gx = sx[n], gy = sy[n];

    // features: 37x37
    float ix = fminf(fmaxf((gx + 1.0f) * 0.5f * (float)(FH - 1), 0.0f), (float)(FH - 1));
    float iy = fminf(fmaxf((gy + 1.0f) * 0.5f * (float)(FH - 1), 0.0f), (float)(FH - 1));
    int x0 = (int)floorf(ix), y0 = (int)floorf(iy);
    int x1 = min(x0 + 1, FH - 1), y1 = min(y0 + 1, FH - 1);
    float wx = ix - (float)x0, wy = iy - (float)y0;
    float w00 = (1.0f - wx) * (1.0f - wy);
    float w01 = wx * (1.0f - wy);
    float w10 = (1.0f - wx) * wy;
    float w11 = wx * wy;

    const float* fb = feat + (size_t)b * CIN * FH * FH;
    for (int c = threadIdx.x; c < CIN; c += blockDim.x) {
        const float* p = fb + (size_t)c * FH * FH;
        float v = p[y0 * FH + x0] * w00 + p[y0 * FH + x1] * w01 +
                  p[y1 * FH + x0] * w10 + p[y1 * FH + x1] * w11;
        g_Fs[(size_t)row * CIN + c] = v;
    }

    if (threadIdx.x == 0) {
        float jx = fminf(fmaxf((gx + 1.0f) * 0.5f * (float)(DHH - 1), 0.0f), (float)(DHH - 1));
        float jy = fminf(fmaxf((gy + 1.0f) * 0.5f * (float)(DHH - 1), 0.0f), (float)(DHH - 1));
        int a0 = (int)floorf(jx), c0 = (int)floorf(jy);
        int a1 = min(a0 + 1, DHH - 1), c1 = min(c0 + 1, DHH - 1);
        float ux = jx - (float)a0, uy = jy - (float)c0;
        const float* dp = depth + (size_t)b * DHH * DHH;
        float v = dp[c0 * DHH + a0] * (1.0f - ux) * (1.0f - uy) +
                  dp[c0 * DHH + a1] * ux * (1.0f - uy) +
                  dp[c1 * DHH + a0] * (1.0f - ux) * uy +
                  dp[c1 * DHH + a1] * ux * uy;
        g_dep[row] = v;
    }
}

// ---------------- generic fused GEMM: C = epi(A[MxK] @ W[KxN] + bias) -------
// EPI: 0 = relu store, 1 = plain store, 2 = state += step * val
// Requires: BM==64, BK==16, K%16==0, M%64==0, TX*TY==256.
template <int BM, int BN, int BK, int TM, int TN, int EPI>
__global__ void gemm_kernel(const float* __restrict__ A,
                            const float* __restrict__ W,
                            const float* __restrict__ bias,
                            float* __restrict__ C,
                            int K, int N,
                            const float* __restrict__ sstep) {
    constexpr int TX = BN / TN;
    constexpr int TY = BM / TM;
    static_assert(TX * TY == 256, "256 threads");
    static_assert(BM == 64 && BK == 16, "A loader assumes 64x16 tile");
    constexpr int AS = BM + 4;  // pad keeps float4 alignment, halves STS conflicts

    __shared__ float As[BK][AS];
    __shared__ float Ws[BK][BN];

    int m0 = blockIdx.x * BM;
    int n0 = blockIdx.y * BN;
    int tid = threadIdx.x;
    int tx = tid % TX, ty = tid / TX;

    float acc[TM][TN];
#pragma unroll
    for (int i = 0; i < TM; i++)
#pragma unroll
        for (int j = 0; j < TN; j++) acc[i][j] = 0.0f;

    int am = tid >> 2;          // 0..63
    int aq = (tid & 3) * 4;     // 0,4,8,12

    for (int k0 = 0; k0 < K; k0 += BK) {
        // stage A tile (vectorized global read, transposed store)
        {
            const float4 v = *reinterpret_cast<const float4*>(
                &A[(size_t)(m0 + am) * K + k0 + aq]);
            As[aq + 0][am] = v.x;
            As[aq + 1][am] = v.y;
            As[aq + 2][am] = v.z;
            As[aq + 3][am] = v.w;
        }
        // stage W tile (coalesced)
        for (int i = tid; i < BK * BN; i += 256) {
            int k = i / BN, n = i % BN;
            Ws[k][n] = W[(size_t)(k0 + k) * N + n0 + n];
        }
        __syncthreads();

#pragma unroll
        for (int kk = 0; kk < BK; kk++) {
            float a[TM], w[TN];
#pragma unroll
            for (int i = 0; i < TM; i++) a[i] = As[kk][ty * TM + i];
#pragma unroll
            for (int j = 0; j < TN; j++) w[j] = Ws[kk][tx * TN + j];
#pragma unroll
            for (int i = 0; i < TM; i++)
#pragma unroll
                for (int j = 0; j < TN; j++) acc[i][j] += a[i] * w[j];
        }
        __syncthreads();
    }

    float step = (EPI == 2) ? sstep[0] : 1.0f;
#pragma unroll
    for (int i = 0; i < TM; i++) {
        int m = m0 + ty * TM + i;
#pragma unroll
        for (int j = 0; j < TN; j++) {
            int n = n0 + tx * TN + j;
            float v = acc[i][j] + bias[n];
            if (EPI == 2) {
                C[(size_t)m * N + n] += step * v;
            } else {
                if (EPI == 0) v = fmaxf(v, 0.0f);
                C[(size_t)m * N + n] = v;
            }
        }
    }
}

// ---------------- initial state build ----------------------------------------
__global__ void init_state_kernel(const float* __restrict__ sx,
                                  const float* __restrict__ sy,
                                  const float* __restrict__ doff) {
    int row = blockIdx.x * blockDim.x + threadIdx.x;
    if (row >= NROWS) return;
    int n = row % NP;
    const float* ini = g_init + (size_t)row * SD;
    float* st = g_state + (size_t)row * SD;
    st[0] = sx[n] + ini[0] * 0.15f;
    st[1] = sy[n] + ini[1] * 0.15f;
    st[2] = doff[0] + g_dep[row] * -2.0f;
#pragma unroll
    for (int i = 3; i < SD; i++) st[i] = ini[i];
}

// ---------------- kNN (block per batch, stable insertion top-7) --------------
__global__ void neigh_kernel() {
    int b = blockIdx.x;
    __shared__ float px[NP], py[NP], pz[NP];
    int t = threadIdx.x;
    if (t < NP) {
        const float* st = g_state + (size_t)(b * NP + t) * SD;
        px[t] = st[0];
        py[t] = st[1];
        pz[t] = st[2];
    }
    __syncthreads();
    if (t >= NP) return;

    float bd[KNEI + 1];
    int bi[KNEI + 1];
#pragma unroll
    for (int i = 0; i <= KNEI; i++) { bd[i] = 3.4e38f; bi[i] = -1; }

    float x = px[t], y = py[t], z = pz[t];
    for (int j = 0; j < NP; j++) {
        float dx = x - px[j], dy = y - py[j], dz = z - pz[j];
        float d2 = dx * dx + dy * dy + dz * dz;
        if (d2 < bd[KNEI]) {   // strict: later equal values lose (matches top_k stability)
            int p = KNEI;
            while (p > 0 && bd[p - 1] > d2) {   // strict: equal keeps earlier index first
                bd[p] = bd[p - 1];
                bi[p] = bi[p - 1];
                p--;
            }
            bd[p] = d2;
            bi[p] = j;
        }
    }
    int* out = g_idx + (size_t)(b * NP + t) * KNEI;
#pragma unroll
    for (int k = 0; k < KNEI; k++) out[k] = bi[k + 1];  // drop self (first)
}

// ---------------- gather pin = [state | 6 neighbor states] -------------------
__global__ void pin_kernel() {
    int t = blockIdx.x * blockDim.x + threadIdx.x;
    if (t >= NROWS * PIN_DIM) return;
    int row = t / PIN_DIM, q = t % PIN_DIM;
    float v;
    if (q < SD) {
        v = g_state[(size_t)row * SD + q];
    } else {
        int k = (q - SD) >> 4;
        int j = (q - SD) & 15;
        int b = row / NP;
        int nb = g_idx[(size_t)row * KNEI + k];
        v = g_state[(size_t)(b * NP + nb) * SD + j];
    }
    g_pin[t] = v;
}

// ---------------- postprocess: pos / softplus scales / rot6d->quat / sigmoid -
__device__ __forceinline__ float sgnf(float x) {
    return (x > 0.0f) ? 1.0f : ((x < 0.0f) ? -1.0f : 0.0f);
}

__global__ void final_kernel(float* __restrict__ out) {
    int row = blockIdx.x * blockDim.x + threadIdx.x;
    if (row >= NROWS) return;
    const float* s = g_state + (size_t)row * SD;
    float o[14];
    o[0] = s[0]; o[1] = s[1]; o[2] = s[2];

#pragma unroll
    for (int i = 0; i < 3; i++) {
        float tv = fminf(fmaxf(s[3 + i], -10.0f), 20.0f) + 1.0f;
        float sp = log1pf(expf(tv));
        o[3 + i] = fminf(fmaxf(sp * 0.15f, 1e-6f), 2.0f);
    }

    const float eps = 1e-8f;
    float a1x = s[6], a1y = s[7], a1z = s[8];
    float a2x = s[9], a2y = s[10], a2z = s[11];
    float n1 = sqrtf(a1x * a1x + a1y * a1y + a1z * a1z) + eps;
    float b1x = a1x / n1, b1y = a1y / n1, b1z = a1z / n1;
    float dd = b1x * a2x + b1y * a2y + b1z * a2z;
    float pxv = a2x - dd * b1x, pyv = a2y - dd * b1y, pzv = a2z - dd * b1z;
    float n2 = sqrtf(pxv * pxv + pyv * pyv + pzv * pzv) + eps;
    float b2x = pxv / n2, b2y = pyv / n2, b2z = pzv / n2;
    float b3x = b1y * b2z - b1z * b2y;
    float b3y = b1z * b2x - b1x * b2z;
    float b3z = b1x * b2y - b1y * b2x;
    float m00 = b1x, m11 = b2y, m22 = b3z;
    float qw = 0.5f * sqrtf(fmaxf(1.0f + m00 + m11 + m22, 0.0f) + eps);
    float qx = 0.5f * sqrtf(fmaxf(1.0f + m00 - m11 - m22, 0.0f) + eps) * sgnf(b2z - b3y);
    float qy = 0.5f * sqrtf(fmaxf(1.0f - m00 + m11 - m22, 0.0f) + eps) * sgnf(b3x - b1z);
    float qz = 0.5f * sqrtf(fmaxf(1.0f - m00 - m11 + m22, 0.0f) + eps) * sgnf(b1y - b2x);
    float qn = sqrtf(qw * qw + qx * qx + qy * qy + qz * qz) + eps;
    o[6] = qw / qn; o[7] = qx / qn; o[8] = qy / qn; o[9] = qz / qn;

    o[10] = 1.0f / (1.0f + expf(-s[12]));
    o[11] = 1.0f / (1.0f + expf(-s[13]));
    o[12] = 1.0f / (1.0f + expf(-s[14]));
    o[13] = 1.0f / (1.0f + expf(-s[15]));

    float* op = out + (size_t)row * 14;
#pragma unroll
    for (int i = 0; i < 14; i++) op[i] = o[i];
}

// ---------------- launch ------------------------------------------------------
extern "C" void kernel_launch(void* const* d_in, const int* in_sizes, int n_in,
                              void* d_out, int out_size) {
    const float* feat  = (const float*)d_in[0];
    const float* depth = (const float*)d_in[1];
    const float* sx    = (const float*)d_in[2];
    const float* sy    = (const float*)d_in[3];
    const float* doff  = (const float*)d_in[4];
    const float* sstep = (const float*)d_in[5];
    const float* wi1 = (const float*)d_in[6];
    const float* bi1 = (const float*)d_in[7];
    const float* wi2 = (const float*)d_in[8];
    const float* bi2 = (const float*)d_in[9];
    const float* wi3 = (const float*)d_in[10];
    const float* bi3 = (const float*)d_in[11];
    const float* wp1 = (const float*)d_in[12];
    const float* bp1 = (const float*)d_in[13];
    const float* wp2 = (const float*)d_in[14];
    const float* bp2 = (const float*)d_in[15];
    const float* wu1 = (const float*)d_in[16];
    const float* bu1 = (const float*)d_in[17];
    const float* wu2 = (const float*)d_in[18];
    const float* bu2 = (const float*)d_in[19];

    void *pFs, *pA, *pB, *pC, *pInit, *pState, *pPin;
    cudaGetSymbolAddress(&pFs, g_Fs);
    cudaGetSymbolAddress(&pA, g_bufA);
    cudaGetSymbolAddress(&pB, g_bufB);
    cudaGetSymbolAddress(&pC, g_bufC);
    cudaGetSymbolAddress(&pInit, g_init);
    cudaGetSymbolAddress(&pState, g_state);
    cudaGetSymbolAddress(&pPin, g_pin);
    float* Fs = (float*)pFs;
    float* bufA = (float*)pA;
    float* bufB = (float*)pB;
    float* bufC = (float*)pC;
    float* initb = (float*)pInit;
    float* state = (float*)pState;
    float* pin = (float*)pPin;

    const int MB = NROWS / 64;  // 377 M-blocks

    // 1) sample
    sample_kernel<<<NROWS, 128>>>(feat, depth, sx, sy);

    // 2) init MLP: 384 -> 256 -> 128 -> 16
    gemm_kernel<64, 64, 16, 4, 4, 0><<<dim3(MB, 4), 256>>>(Fs, wi1, bi1, bufA, CIN, H2X, nullptr);
    gemm_kernel<64, 64, 16, 4, 4, 0><<<dim3(MB, 2), 256>>>(bufA, wi2, bi2, bufB, H2X, HID, nullptr);
    gemm_kernel<64, 16, 16, 4, 1, 1><<<dim3(MB, 1), 256>>>(bufB, wi3, bi3, initb, HID, SD, nullptr);

    // 3) initial state
    init_state_kernel<<<(NROWS + 255) / 256, 256>>>(sx, sy, doff);

    // 4) NCA steps
    for (int s = 0; s < NSTEPS; s++) {
        neigh_kernel<<<BB, 384>>>();
        pin_kernel<<<(NROWS * PIN_DIM + 255) / 256, 256>>>();
        gemm_kernel<64, 64, 16, 4, 4, 0><<<dim3(MB, 4), 256>>>(pin, wp1, bp1, bufA, PIN_DIM, H2X, nullptr);
        gemm_kernel<64, 64, 16, 4, 4, 0><<<dim3(MB, 2), 256>>>(bufA, wp2, bp2, bufB, H2X, HID, nullptr);
        gemm_kernel<64, 64, 16, 4, 4, 0><<<dim3(MB, 2), 256>>>(bufB, wu1, bu1, bufC, HID, HID, nullptr);
        gemm_kernel<64, 16, 16, 4, 1, 2><<<dim3(MB, 1), 256>>>(bufC, wu2, bu2, state, HID, SD, sstep);
    }

    // 5) postprocess
    final_kernel<<<(NROWS + 255) / 256, 256>>>((float*)d_out);
}

// round 2
// speedup vs baseline: 1.0039x; 1.0039x over previous
#include <cuda_runtime.h>
#include <math.h>

// ---------------- problem constants ----------------
#define BB      64
#define NP      377
#define NROWS   (BB * NP)        // 24128 = 377 * 64
#define CIN     384
#define HID     128
#define H2X     256
#define SD      16
#define KNEI    6
#define PIN_DIM (SD * (KNEI + 1)) // 112
#define NSTEPS  16
#define FH      37
#define DHH     518

// ---------------- scratch (static device memory; no allocation) -------------
__device__ float g_Fs[(size_t)NROWS * CIN];
__device__ float g_dep[NROWS];
__device__ float g_bufA[(size_t)NROWS * H2X];   // h1 (256 wide)
__device__ float g_bufB[(size_t)NROWS * HID];   // init path only
__device__ float g_init[(size_t)NROWS * SD];
__device__ float g_state[(size_t)NROWS * SD];
__device__ float g_pin[(size_t)NROWS * PIN_DIM];

// ---------------- bilinear sampling (features + depth) ----------------------
__global__ void sample_kernel(const float* __restrict__ feat,
                              const float* __restrict__ depth,
                              const float* __restrict__ sx,
                              const float* __restrict__ sy) {
    int row = blockIdx.x;
    int b = row / NP, n = row % NP;
    float gx = sx[n], gy = sy[n];

    float ix = fminf(fmaxf((gx + 1.0f) * 0.5f * (float)(FH - 1), 0.0f), (float)(FH - 1));
    float iy = fminf(fmaxf((gy + 1.0f) * 0.5f * (float)(FH - 1), 0.0f), (float)(FH - 1));
    int x0 = (int)floorf(ix), y0 = (int)floorf(iy);
    int x1 = min(x0 + 1, FH - 1), y1 = min(y0 + 1, FH - 1);
    float wx = ix - (float)x0, wy = iy - (float)y0;
    float w00 = (1.0f - wx) * (1.0f - wy);
    float w01 = wx * (1.0f - wy);
    float w10 = (1.0f - wx) * wy;
    float w11 = wx * wy;

    const float* fb = feat + (size_t)b * CIN * FH * FH;
    for (int c = threadIdx.x; c < CIN; c += blockDim.x) {
        const float* p = fb + (size_t)c * FH * FH;
        float v = p[y0 * FH + x0] * w00 + p[y0 * FH + x1] * w01 +
                  p[y1 * FH + x0] * w10 + p[y1 * FH + x1] * w11;
        g_Fs[(size_t)row * CIN + c] = v;
    }

    if (threadIdx.x == 0) {
        float jx = fminf(fmaxf((gx + 1.0f) * 0.5f * (float)(DHH - 1), 0.0f), (float)(DHH - 1));
        float jy = fminf(fmaxf((gy + 1.0f) * 0.5f * (float)(DHH - 1), 0.0f), (float)(DHH - 1));
        int a0 = (int)floorf(jx), c0 = (int)floorf(jy);
        int a1 = min(a0 + 1, DHH - 1), c1 = min(c0 + 1, DHH - 1);
        float ux = jx - (float)a0, uy = jy - (float)c0;
        const float* dp = depth + (size_t)b * DHH * DHH;
        float v = dp[c0 * DHH + a0] * (1.0f - ux) * (1.0f - uy) +
                  dp[c0 * DHH + a1] * ux * (1.0f - uy) +
                  dp[c1 * DHH + a0] * (1.0f - ux) * uy +
                  dp[c1 * DHH + a1] * ux * uy;
        g_dep[row] = v;
    }
}

// ---------------- 64x128 GEMM, 128 threads, 8x8 microtile --------------------
// C[64x128 tile] = epi(A[MxK] @ W[KxN] + bias). EPI: 0 relu, 1 none.
// K % 16 == 0, M % 64 == 0, N % 128 == 0 for the tiles launched.
template <int EPI>
__global__ void __launch_bounds__(128)
gemm64x128(const float* __restrict__ A, const float* __restrict__ W,
           const float* __restrict__ bias, float* __restrict__ C,
           int K, int N) {
    __shared__ float As[16][68];
    __shared__ float Ws[16][128];

    int m0 = blockIdx.x * 64;
    int n0 = blockIdx.y * 128;
    int tid = threadIdx.x;
    int r8  = tid & 7;    // row group: rows r8*8 .. +7
    int c16 = tid >> 3;   // col group: cols c16*8 .. +7

    float acc[8][8];
#pragma unroll
    for (int i = 0; i < 8; i++)
#pragma unroll
        for (int j = 0; j < 8; j++) acc[i][j] = 0.0f;

    for (int k0 = 0; k0 < K; k0 += 16) {
        // stage A 64x16 (transposed), 2 float4 per thread
#pragma unroll
        for (int i = 0; i < 2; i++) {
            int f = tid + i * 128;
            int am = f >> 2, aq = (f & 3) * 4;
            float4 v = *reinterpret_cast<const float4*>(&A[(size_t)(m0 + am) * K + k0 + aq]);
            As[aq + 0][am] = v.x;
            As[aq + 1][am] = v.y;
            As[aq + 2][am] = v.z;
            As[aq + 3][am] = v.w;
        }
        // stage W 16x128, 4 float4 per thread (coalesced)
#pragma unroll
        for (int i = 0; i < 4; i++) {
            int f = tid + i * 128;
            int k = f >> 5, n = (f & 31) * 4;
            *reinterpret_cast<float4*>(&Ws[k][n]) =
                *reinterpret_cast<const float4*>(&W[(size_t)(k0 + k) * N + n0 + n]);
        }
        __syncthreads();

#pragma unroll
        for (int kk = 0; kk < 16; kk++) {
            float a[8], w[8];
            float4 a0 = *reinterpret_cast<const float4*>(&As[kk][r8 * 8]);
            float4 a1 = *reinterpret_cast<const float4*>(&As[kk][r8 * 8 + 4]);
            float4 w0 = *reinterpret_cast<const float4*>(&Ws[kk][c16 * 8]);
            float4 w1 = *reinterpret_cast<const float4*>(&Ws[kk][c16 * 8 + 4]);
            a[0]=a0.x; a[1]=a0.y; a[2]=a0.z; a[3]=a0.w;
            a[4]=a1.x; a[5]=a1.y; a[6]=a1.z; a[7]=a1.w;
            w[0]=w0.x; w[1]=w0.y; w[2]=w0.z; w[3]=w0.w;
            w[4]=w1.x; w[5]=w1.y; w[6]=w1.z; w[7]=w1.w;
#pragma unroll
            for (int i = 0; i < 8; i++)
#pragma unroll
                for (int j = 0; j < 8; j++) acc[i][j] += a[i] * w[j];
        }
        __syncthreads();
    }

    float bb[8];
#pragma unroll
    for (int j = 0; j < 8; j++) bb[j] = bias[n0 + c16 * 8 + j];
#pragma unroll
    for (int i = 0; i < 8; i++) {
        int m = m0 + r8 * 8 + i;
        float v[8];
#pragma unroll
        for (int j = 0; j < 8; j++) {
            v[j] = acc[i][j] + bb[j];
            if (EPI == 0) v[j] = fmaxf(v[j], 0.0f);
        }
        float4* cp = reinterpret_cast<float4*>(&C[(size_t)m * N + n0 + c16 * 8]);
        cp[0] = make_float4(v[0], v[1], v[2], v[3]);
        cp[1] = make_float4(v[4], v[5], v[6], v[7]);
    }
}

// ---------------- legacy small GEMM (N=16), used once for wi3 ----------------
template <int BM, int BN, int BK, int TM, int TN, int EPI>
__global__ void gemm_kernel(const float* __restrict__ A,
                            const float* __restrict__ W,
                            const float* __restrict__ bias,
                            float* __restrict__ C,
                            int K, int N) {
    constexpr int TX = BN / TN;
    constexpr int TY = BM / TM;
    static_assert(TX * TY == 256, "256 threads");
    constexpr int AS = BM + 4;
    __shared__ float As[BK][AS];
    __shared__ float Ws[BK][BN];

    int m0 = blockIdx.x * BM;
    int n0 = blockIdx.y * BN;
    int tid = threadIdx.x;
    int tx = tid % TX, ty = tid / TX;

    float acc[TM][TN];
#pragma unroll
    for (int i = 0; i < TM; i++)
#pragma unroll
        for (int j = 0; j < TN; j++) acc[i][j] = 0.0f;

    int am = tid >> 2;
    int aq = (tid & 3) * 4;

    for (int k0 = 0; k0 < K; k0 += BK) {
        {
            const float4 v = *reinterpret_cast<const float4*>(
                &A[(size_t)(m0 + am) * K + k0 + aq]);
            As[aq + 0][am] = v.x;
            As[aq + 1][am] = v.y;
            As[aq + 2][am] = v.z;
            As[aq + 3][am] = v.w;
        }
        for (int i = tid; i < BK * BN; i += 256) {
            int k = i / BN, n = i % BN;
            Ws[k][n] = W[(size_t)(k0 + k) * N + n0 + n];
        }
        __syncthreads();
#pragma unroll
        for (int kk = 0; kk < BK; kk++) {
            float a[TM], w[TN];
#pragma unroll
            for (int i = 0; i < TM; i++) a[i] = As[kk][ty * TM + i];
#pragma unroll
            for (int j = 0; j < TN; j++) w[j] = Ws[kk][tx * TN + j];
#pragma unroll
            for (int i = 0; i < TM; i++)
#pragma unroll
                for (int j = 0; j < TN; j++) acc[i][j] += a[i] * w[j];
        }
        __syncthreads();
    }
#pragma unroll
    for (int i = 0; i < TM; i++) {
        int m = m0 + ty * TM + i;
#pragma unroll
        for (int j = 0; j < TN; j++) {
            int n = n0 + tx * TN + j;
            float v = acc[i][j] + bias[n];
            if (EPI == 0) v = fmaxf(v, 0.0f);
            C[(size_t)m * N + n] = v;
        }
    }
}

// ---------------- fused wp2 -> wu1 -> wu2 -> state update --------------------
// Per block: 64 rows. h1 (global, 256 wide) -> h2 (smem 128) -> dh (smem 128)
// -> delta (16) -> state += step*delta.
__global__ void __launch_bounds__(128)
fused_step(const float* __restrict__ A,           // g_bufA (h1), row len 256
           const float* __restrict__ wp2, const float* __restrict__ bp2,
           const float* __restrict__ wu1, const float* __restrict__ bu1,
           const float* __restrict__ wu2, const float* __restrict__ bu2,
           const float* __restrict__ sstep,
           float* __restrict__ state) {
    __shared__ float As[16][68];
    __shared__ float Ws[2048];          // 16x128 weight staging / 128x16 wu2
    __shared__ float Hs[128][68];       // h2 then dh, stored [k][m]
    __shared__ float bp2s[128], bu1s[128], bu2s[16];

    int m0 = blockIdx.x * 64;
    int tid = threadIdx.x;
    int r8  = tid & 7;
    int c16 = tid >> 3;

    if (tid < 128) { bp2s[tid] = bp2[tid]; bu1s[tid] = bu1[tid]; }
    if (tid < 16)  { bu2s[tid] = bu2[tid]; }

    float acc[8][8];
#pragma unroll
    for (int i = 0; i < 8; i++)
#pragma unroll
        for (int j = 0; j < 8; j++) acc[i][j] = 0.0f;

    // ---- phase 1: h2 = relu(h1 @ wp2 + bp2), K=256 ----
    for (int k0 = 0; k0 < 256; k0 += 16) {
#pragma unroll
        for (int i = 0; i < 2; i++) {
            int f = tid + i * 128;
            int am = f >> 2, aq = (f & 3) * 4;
            float4 v = *reinterpret_cast<const float4*>(&A[(size_t)(m0 + am) * 256 + k0 + aq]);
            As[aq + 0][am] = v.x;
            As[aq + 1][am] = v.y;
            As[aq + 2][am] = v.z;
            As[aq + 3][am] = v.w;
        }
#pragma unroll
        for (int i = 0; i < 4; i++) {
            int f = tid + i * 128;
            int k = f >> 5, n = (f & 31) * 4;
            *reinterpret_cast<float4*>(&Ws[k * 128 + n]) =
                *reinterpret_cast<const float4*>(&wp2[(size_t)(k0 + k) * 128 + n]);
        }
        __syncthreads();
#pragma unroll
        for (int kk = 0; kk < 16; kk++) {
            float4 a0 = *reinterpret_cast<const float4*>(&As[kk][r8 * 8]);
            float4 a1 = *reinterpret_cast<const float4*>(&As[kk][r8 * 8 + 4]);
            float4 w0 = *reinterpret_cast<const float4*>(&Ws[kk * 128 + c16 * 8]);
            float4 w1 = *reinterpret_cast<const float4*>(&Ws[kk * 128 + c16 * 8 + 4]);
            float a[8] = {a0.x,a0.y,a0.z,a0.w,a1.x,a1.y,a1.z,a1.w};
            float w[8] = {w0.x,w0.y,w0.z,w0.w,w1.x,w1.y,w1.z,w1.w};
#pragma unroll
            for (int i = 0; i < 8; i++)
#pragma unroll
                for (int j = 0; j < 8; j++) acc[i][j] += a[i] * w[j];
        }
        __syncthreads();
    }
    // epilogue 1: transposed store into Hs[k=n][m]
#pragma unroll
    for (int j = 0; j < 8; j++) {
        int n = c16 * 8 + j;
        float v[8];
#pragma unroll
        for (int i = 0; i < 8; i++) v[i] = fmaxf(acc[i][j] + bp2s[n], 0.0f);
        float4* hp = reinterpret_cast<float4*>(&Hs[n][r8 * 8]);
        hp[0] = make_float4(v[0], v[1], v[2], v[3]);
        hp[1] = make_float4(v[4], v[5], v[6], v[7]);
    }
    __syncthreads();

    // ---- phase 2: dh = relu(h2 @ wu1 + bu1), K=128, A already in Hs ----
#pragma unroll
    for (int i = 0; i < 8; i++)
#pragma unroll
        for (int j = 0; j < 8; j++) acc[i][j] = 0.0f;

    for (int c = 0; c < 8; c++) {
#pragma unroll
        for (int i = 0; i < 4; i++) {
            int f = tid + i * 128;
            int k = f >> 5, n = (f & 31) * 4;
            *reinterpret_cast<float4*>(&Ws[k * 128 + n]) =
                *reinterpret_cast<const float4*>(&wu1[(size_t)(c * 16 + k) * 128 + n]);
        }
        __syncthreads();
#pragma unroll
        for (int kk = 0; kk < 16; kk++) {
            float4 a0 = *reinterpret_cast<const float4*>(&Hs[c * 16 + kk][r8 * 8]);
            float4 a1 = *reinterpret_cast<const float4*>(&Hs[c * 16 + kk][r8 * 8 + 4]);
            float4 w0 = *reinterpret_cast<const float4*>(&Ws[kk * 128 + c16 * 8]);
            float4 w1 = *reinterpret_cast<const float4*>(&Ws[kk * 128 + c16 * 8 + 4]);
            float a[8] = {a0.x,a0.y,a0.z,a0.w,a1.x,a1.y,a1.z,a1.w};
            float w[8] = {w0.x,w0.y,w0.z,w0.w,w1.x,w1.y,w1.z,w1.w};
#pragma unroll
            for (int i = 0; i < 8; i++)
#pragma unroll
                for (int j = 0; j < 8; j++) acc[i][j] += a[i] * w[j];
        }
        __syncthreads();
    }
    // epilogue 2: overwrite Hs with dh (all reads finished at last sync)
#pragma unroll
    for (int j = 0; j < 8; j++) {
        int n = c16 * 8 + j;
        float v[8];
#pragma unroll
        for (int i = 0; i < 8; i++) v[i] = fmaxf(acc[i][j] + bu1s[n], 0.0f);
        float4* hp = reinterpret_cast<float4*>(&Hs[n][r8 * 8]);
        hp[0] = make_float4(v[0], v[1], v[2], v[3]);
        hp[1] = make_float4(v[4], v[5], v[6], v[7]);
    }
    // stage wu2 (128x16) into Ws
#pragma unroll
    for (int i = 0; i < 4; i++) {
        int f = (tid + i * 128) * 4;   // 2048 floats
        *reinterpret_cast<float4*>(&Ws[f]) =
            *reinterpret_cast<const float4*>(&wu2[f]);
    }
    __syncthreads();

    // ---- phase 3: delta = dh @ wu2 + bu2; state += step*delta ----
    {
        int col = tid & 15;
        int rg  = tid >> 4;   // 0..7 -> rows rg*8..+7
        float acc3[8];
#pragma unroll
        for (int i = 0; i < 8; i++) acc3[i] = 0.0f;
        for (int kk = 0; kk < 128; kk++) {
            float w = Ws[kk * 16 + col];
            float4 a0 = *reinterpret_cast<const float4*>(&Hs[kk][rg * 8]);
            float4 a1 = *reinterpret_cast<const float4*>(&Hs[kk][rg * 8 + 4]);
            acc3[0] += a0.x * w; acc3[1] += a0.y * w;
            acc3[2] += a0.z * w; acc3[3] += a0.w * w;
            acc3[4] += a1.x * w; acc3[5] += a1.y * w;
            acc3[6] += a1.z * w; acc3[7] += a1.w * w;
        }
        float stp = sstep[0];
        float bv = bu2s[col];
#pragma unroll
        for (int i = 0; i < 8; i++) {
            int m = m0 + rg * 8 + i;
            state[(size_t)m * SD + col] += stp * (acc3[i] + bv);
        }
    }
}

// ---------------- initial state build ----------------------------------------
__global__ void init_state_kernel(const float* __restrict__ sx,
                                  const float* __restrict__ sy,
                                  const float* __restrict__ doff) {
    int row = blockIdx.x * blockDim.x + threadIdx.x;
    if (row >= NROWS) return;
    int n = row % NP;
    const float* ini = g_init + (size_t)row * SD;
    float* st = g_state + (size_t)row * SD;
    st[0] = sx[n] + ini[0] * 0.15f;
    st[1] = sy[n] + ini[1] * 0.15f;
    st[2] = doff[0] + g_dep[row] * -2.0f;
#pragma unroll
    for (int i = 3; i < SD; i++) st[i] = ini[i];
}

// ---------------- fused kNN + pin gather (block per batch) -------------------
__global__ void __launch_bounds__(384) neighpin_kernel() {
    __shared__ float st[NP * SD];   // 24128 B
    int b = blockIdx.x, t = threadIdx.x;

    const float4* gs = reinterpret_cast<const float4*>(g_state + (size_t)b * NP * SD);
    float4* s4 = reinterpret_cast<float4*>(st);
    for (int i = t; i < NP * SD / 4; i += 384) s4[i] = gs[i];
    __syncthreads();
    if (t >= NP) return;

    float bd[KNEI + 1];
    int bi[KNEI + 1];
#pragma unroll
    for (int i = 0; i <= KNEI; i++) { bd[i] = 3.4e38f; bi[i] = -1; }

    float x = st[t * SD + 0], y = st[t * SD + 1], z = st[t * SD + 2];
    for (int j = 0; j < NP; j++) {
        float dx = x - st[j * SD + 0];
        float dy = y - st[j * SD + 1];
        float dz = z - st[j * SD + 2];
        float d2 = dx * dx + dy * dy + dz * dz;
        if (d2 < bd[KNEI]) {
            int p = KNEI;
            while (p > 0 && bd[p - 1] > d2) {
                bd[p] = bd[p - 1];
                bi[p] = bi[p - 1];
                p--;
            }
            bd[p] = d2;
            bi[p] = j;
        }
    }

    float4* p4 = reinterpret_cast<float4*>(g_pin + (size_t)(b * NP + t) * PIN_DIM);
    const float4* self = reinterpret_cast<const float4*>(&st[t * SD]);
#pragma unroll
    for (int q = 0; q < 4; q++) p4[q] = self[q];
#pragma unroll
    for (int k = 0; k < KNEI; k++) {
        const float4* nb = reinterpret_cast<const float4*>(&st[bi[k + 1] * SD]);
#pragma unroll
        for (int q = 0; q < 4; q++) p4[4 + k * 4 + q] = nb[q];
    }
}

// ---------------- postprocess ------------------------------------------------
__device__ __forceinline__ float sgnf(float x) {
    return (x > 0.0f) ? 1.0f : ((x < 0.0f) ? -1.0f : 0.0f);
}

__global__ void final_kernel(float* __restrict__ out) {
    int row = blockIdx.x * blockDim.x + threadIdx.x;
    if (row >= NROWS) return;
    const float* s = g_state + (size_t)row * SD;
    float o[14];
    o[0] = s[0]; o[1] = s[1]; o[2] = s[2];

#pragma unroll
    for (int i = 0; i < 3; i++) {
        float tv = fminf(fmaxf(s[3 + i], -10.0f), 20.0f) + 1.0f;
        float sp = log1pf(expf(tv));
        o[3 + i] = fminf(fmaxf(sp * 0.15f, 1e-6f), 2.0f);
    }

    const float eps = 1e-8f;
    float a1x = s[6], a1y = s[7], a1z = s[8];
    float a2x = s[9], a2y = s[10], a2z = s[11];
    float n1 = sqrtf(a1x * a1x + a1y * a1y + a1z * a1z) + eps;
    float b1x = a1x / n1, b1y = a1y / n1, b1z = a1z / n1;
    float dd = b1x * a2x + b1y * a2y + b1z * a2z;
    float pxv = a2x - dd * b1x, pyv = a2y - dd * b1y, pzv = a2z - dd * b1z;
    float n2 = sqrtf(pxv * pxv + pyv * pyv + pzv * pzv) + eps;
    float b2x = pxv / n2, b2y = pyv / n2, b2z = pzv / n2;
    float b3x = b1y * b2z - b1z * b2y;
    float b3y = b1z * b2x - b1x * b2z;
    float b3z = b1x * b2y - b1y * b2x;
    float m00 = b1x, m11 = b2y, m22 = b3z;
    float qw = 0.5f * sqrtf(fmaxf(1.0f + m00 + m11 + m22, 0.0f) + eps);
    float qx = 0.5f * sqrtf(fmaxf(1.0f + m00 - m11 - m22, 0.0f) + eps) * sgnf(b2z - b3y);
    float qy = 0.5f * sqrtf(fmaxf(1.0f - m00 + m11 - m22, 0.0f) + eps) * sgnf(b3x - b1z);
    float qz = 0.5f * sqrtf(fmaxf(1.0f - m00 - m11 + m22, 0.0f) + eps) * sgnf(b1y - b2x);
    float qn = sqrtf(qw * qw + qx * qx + qy * qy + qz * qz) + eps;
    o[6] = qw / qn; o[7] = qx / qn; o[8] = qy / qn; o[9] = qz / qn;

    o[10] = 1.0f / (1.0f + expf(-s[12]));
    o[11] = 1.0f / (1.0f + expf(-s[13]));
    o[12] = 1.0f / (1.0f + expf(-s[14]));
    o[13] = 1.0f / (1.0f + expf(-s[15]));

    float* op = out + (size_t)row * 14;
#pragma unroll
    for (int i = 0; i < 14; i++) op[i] = o[i];
}

// ---------------- launch ------------------------------------------------------
extern "C" void kernel_launch(void* const* d_in, const int* in_sizes, int n_in,
                              void* d_out, int out_size) {
    const float* feat  = (const float*)d_in[0];
    const float* depth = (const float*)d_in[1];
    const float* sx    = (const float*)d_in[2];
    const float* sy    = (const float*)d_in[3];
    const float* doff  = (const float*)d_in[4];
    const float* sstep = (const float*)d_in[5];
    const float* wi1 = (const float*)d_in[6];
    const float* bi1 = (const float*)d_in[7];
    const float* wi2 = (const float*)d_in[8];
    const float* bi2 = (const float*)d_in[9];
    const float* wi3 = (const float*)d_in[10];
    const float* bi3 = (const float*)d_in[11];
    const float* wp1 = (const float*)d_in[12];
    const float* bp1 = (const float*)d_in[13];
    const float* wp2 = (const float*)d_in[14];
    const float* bp2 = (const float*)d_in[15];
    const float* wu1 = (const float*)d_in[16];
    const float* bu1 = (const float*)d_in[17];
    const float* wu2 = (const float*)d_in[18];
    const float* bu2 = (const float*)d_in[19];

    void *pFs, *pA, *pB, *pInit, *pState, *pPin;
    cudaGetSymbolAddress(&pFs, g_Fs);
    cudaGetSymbolAddress(&pA, g_bufA);
    cudaGetSymbolAddress(&pB, g_bufB);
    cudaGetSymbolAddress(&pInit, g_init);
    cudaGetSymbolAddress(&pState, g_state);
    cudaGetSymbolAddress(&pPin, g_pin);
    float* Fs = (float*)pFs;
    float* bufA = (float*)pA;
    float* bufB = (float*)pB;
    float* initb = (float*)pInit;
    float* state = (float*)pState;
    float* pin = (float*)pPin;

    const int MB = NROWS / 64;  // 377

    // 1) sample
    sample_kernel<<<NROWS, 128>>>(feat, depth, sx, sy);

    // 2) init MLP: 384 -> 256 -> 128 -> 16
    gemm64x128<0><<<dim3(MB, 2), 128>>>(Fs, wi1, bi1, bufA, CIN, H2X);
    gemm64x128<0><<<dim3(MB, 1), 128>>>(bufA, wi2, bi2, bufB, H2X, HID);
    gemm_kernel<64, 16, 16, 4, 1, 1><<<dim3(MB, 1), 256>>>(bufB, wi3, bi3, initb, HID, SD);

    // 3) initial state
    init_state_kernel<<<(NROWS + 255) / 256, 256>>>(sx, sy, doff);

    // 4) NCA steps
    for (int s = 0; s < NSTEPS; s++) {
        neighpin_kernel<<<BB, 384>>>();
        gemm64x128<0><<<dim3(MB, 2), 128>>>(pin, wp1, bp1, bufA, PIN_DIM, H2X);
        fused_step<<<MB, 128>>>(bufA, wp2, bp2, wu1, bu1, wu2, bu2, sstep, state);
    }

    // 5) postprocess
    final_kernel<<<(NROWS + 255) / 256, 256>>>((float*)d_out);
}

// round 4
// speedup vs baseline: 1.3391x; 1.3339x over previous
#include <cuda_runtime.h>
#include <math.h>

// ---------------- problem constants ----------------
#define BB      64
#define NP      377
#define NROWS   (BB * NP)        // 24128 = 377 * 64
#define CIN     384
#define HID     128
#define H2X     256
#define SD      16
#define KNEI    6
#define PIN_DIM (SD * (KNEI + 1)) // 112
#define NSTEPS  16
#define FH      37
#define DHH     518

// fused_step dynamic smem layout (floats)
#define FS_AS_OFF   0                       // As[2][16][68]  = 2176
#define FS_WS_OFF   2176                    // Ws[2][16][128] = 4096
#define FS_HS_OFF   (2176 + 4096)           // Hs[128][68]    = 8704
#define FS_B1_OFF   (FS_HS_OFF + 8704)      // bp2s[128]
#define FS_B2_OFF   (FS_B1_OFF + 128)       // bu1s[128]
#define FS_B3_OFF   (FS_B2_OFF + 128)       // bu2s[16]
#define FS_TOTAL_F  (FS_B3_OFF + 16)        // 15248 floats
#define FS_TOTAL_B  (FS_TOTAL_F * 4)        // 60992 bytes

// ---------------- scratch (static device memory; no allocation) -------------
__device__ float g_Fs[(size_t)NROWS * CIN];
__device__ float g_dep[NROWS];
__device__ float g_bufA[(size_t)NROWS * H2X];   // h1 (256 wide)
__device__ float g_bufB[(size_t)NROWS * HID];   // init path only
__device__ float g_init[(size_t)NROWS * SD];
__device__ float g_state[(size_t)NROWS * SD];
__device__ float g_pin[(size_t)NROWS * PIN_DIM];

// ---------------- feature bilinear sampling ----------------------------------
__global__ void sample_feat_kernel(const float* __restrict__ feat,
                                   const float* __restrict__ sx,
                                   const float* __restrict__ sy) {
    int row = blockIdx.x;
    int b = row / NP, n = row % NP;
    float gx = sx[n], gy = sy[n];

    float ix = fminf(fmaxf((gx + 1.0f) * 0.5f * (float)(FH - 1), 0.0f), (float)(FH - 1));
    float iy = fminf(fmaxf((gy + 1.0f) * 0.5f * (float)(FH - 1), 0.0f), (float)(FH - 1));
    int x0 = (int)floorf(ix), y0 = (int)floorf(iy);
    int x1 = min(x0 + 1, FH - 1), y1 = min(y0 + 1, FH - 1);
    float wx = ix - (float)x0, wy = iy - (float)y0;
    float w00 = (1.0f - wx) * (1.0f - wy);
    float w01 = wx * (1.0f - wy);
    float w10 = (1.0f - wx) * wy;
    float w11 = wx * wy;

    const float* fb = feat + (size_t)b * CIN * FH * FH;
    for (int c = threadIdx.x; c < CIN; c += blockDim.x) {
        const float* p = fb + (size_t)c * FH * FH;
        float v = p[y0 * FH + x0] * w00 + p[y0 * FH + x1] * w01 +
                  p[y1 * FH + x0] * w10 + p[y1 * FH + x1] * w11;
        g_Fs[(size_t)row * CIN + c] = v;
    }
}

// ---------------- depth bilinear sampling ------------------------------------
__global__ void sample_depth_kernel(const float* __restrict__ depth,
                                    const float* __restrict__ sx,
                                    const float* __restrict__ sy) {
    int row = blockIdx.x * blockDim.x + threadIdx.x;
    if (row >= NROWS) return;
    int b = row / NP, n = row % NP;
    float gx = sx[n], gy = sy[n];
    float jx = fminf(fmaxf((gx + 1.0f) * 0.5f * (float)(DHH - 1), 0.0f), (float)(DHH - 1));
    float jy = fminf(fmaxf((gy + 1.0f) * 0.5f * (float)(DHH - 1), 0.0f), (float)(DHH - 1));
    int a0 = (int)floorf(jx), c0 = (int)floorf(jy);
    int a1 = min(a0 + 1, DHH - 1), c1 = min(c0 + 1, DHH - 1);
    float ux = jx - (float)a0, uy = jy - (float)c0;
    const float* dp = depth + (size_t)b * DHH * DHH;
    float v = dp[c0 * DHH + a0] * (1.0f - ux) * (1.0f - uy) +
              dp[c0 * DHH + a1] * ux * (1.0f - uy) +
              dp[c1 * DHH + a0] * (1.0f - ux) * uy +
              dp[c1 * DHH + a1] * ux * uy;
    g_dep[row] = v;
}

// ---------------- 64x128 GEMM, 128 threads, 8x8 microtile, double-buffered ---
template <int EPI>
__global__ void __launch_bounds__(128)
gemm64x128(const float* __restrict__ A, const float* __restrict__ W,
           const float* __restrict__ bias, float* __restrict__ C,
           int K, int N) {
    __shared__ float As[2][16][68];
    __shared__ float Ws[2][16][128];

    int m0 = blockIdx.x * 64;
    int n0 = blockIdx.y * 128;
    int tid = threadIdx.x;
    int r8 = tid & 7, c16 = tid >> 3;

    int am0 = tid >> 2;            // 0..31; second A row group at +32
    int aq  = (tid & 3) * 4;       // 0,4,8,12
    int wk  = tid >> 5;            // 0..3
    int wn  = (tid & 31) * 4;

    float acc[8][8];
#pragma unroll
    for (int i = 0; i < 8; i++)
#pragma unroll
        for (int j = 0; j < 8; j++) acc[i][j] = 0.0f;

    // preload tile 0
#pragma unroll
    for (int i = 0; i < 2; i++) {
        int am = am0 + i * 32;
        float4 v = *reinterpret_cast<const float4*>(&A[(size_t)(m0 + am) * K + aq]);
        As[0][aq + 0][am] = v.x;
        As[0][aq + 1][am] = v.y;
        As[0][aq + 2][am] = v.z;
        As[0][aq + 3][am] = v.w;
    }
#pragma unroll
    for (int i = 0; i < 4; i++) {
        int k = wk + i * 4;
        *reinterpret_cast<float4*>(&Ws[0][k][wn]) =
            *reinterpret_cast<const float4*>(&W[(size_t)k * N + n0 + wn]);
    }
    __syncthreads();

    int KT = K >> 4;
    int p = 0;
    for (int t = 0; t < KT; t++) {
        float4 pa[2], pw[4];
        bool has = (t + 1 < KT);
        if (has) {
            int k0 = (t + 1) << 4;
#pragma unroll
            for (int i = 0; i < 2; i++)
                pa[i] = *reinterpret_cast<const float4*>(
                    &A[(size_t)(m0 + am0 + i * 32) * K + k0 + aq]);
#pragma unroll
            for (int i = 0; i < 4; i++)
                pw[i] = *reinterpret_cast<const float4*>(
                    &W[(size_t)(k0 + wk + i * 4) * N + n0 + wn]);
        }

#pragma unroll
        for (int kk = 0; kk < 16; kk++) {
            float4 a0 = *reinterpret_cast<const float4*>(&As[p][kk][r8 * 4]);
            float4 a1 = *reinterpret_cast<const float4*>(&As[p][kk][32 + r8 * 4]);
            float4 w0 = *reinterpret_cast<const float4*>(&Ws[p][kk][c16 * 8]);
            float4 w1 = *reinterpret_cast<const float4*>(&Ws[p][kk][c16 * 8 + 4]);
            float a[8] = {a0.x,a0.y,a0.z,a0.w,a1.x,a1.y,a1.z,a1.w};
            float w[8] = {w0.x,w0.y,w0.z,w0.w,w1.x,w1.y,w1.z,w1.w};
#pragma unroll
            for (int i = 0; i < 8; i++)
#pragma unroll
                for (int j = 0; j < 8; j++) acc[i][j] += a[i] * w[j];
        }

        if (has) {
            int q = p ^ 1;
#pragma unroll
            for (int i = 0; i < 2; i++) {
                int am = am0 + i * 32;
                As[q][aq + 0][am] = pa[i].x;
                As[q][aq + 1][am] = pa[i].y;
                As[q][aq + 2][am] = pa[i].z;
                As[q][aq + 3][am] = pa[i].w;
            }
#pragma unroll
            for (int i = 0; i < 4; i++)
                *reinterpret_cast<float4*>(&Ws[q][wk + i * 4][wn]) = pw[i];
        }
        __syncthreads();
        p ^= 1;
    }

    float bb[8];
#pragma unroll
    for (int j = 0; j < 8; j++) bb[j] = bias[n0 + c16 * 8 + j];
#pragma unroll
    for (int h = 0; h < 2; h++) {
#pragma unroll
        for (int i = 0; i < 4; i++) {
            int m = m0 + h * 32 + r8 * 4 + i;
            int ai = h * 4 + i;
            float v[8];
#pragma unroll
            for (int j = 0; j < 8; j++) {
                v[j] = acc[ai][j] + bb[j];
                if (EPI == 0) v[j] = fmaxf(v[j], 0.0f);
            }
            float4* cp = reinterpret_cast<float4*>(&C[(size_t)m * N + n0 + c16 * 8]);
            cp[0] = make_float4(v[0], v[1], v[2], v[3]);
            cp[1] = make_float4(v[4], v[5], v[6], v[7]);
        }
    }
}

// ---------------- small GEMM (N=16), used once for wi3 -----------------------
template <int BM, int BN, int BK, int TM, int TN, int EPI>
__global__ void gemm_kernel(const float* __restrict__ A,
                            const float* __restrict__ W,
                            const float* __restrict__ bias,
                            float* __restrict__ C,
                            int K, int N) {
    constexpr int TX = BN / TN;
    constexpr int TY = BM / TM;
    static_assert(TX * TY == 256, "256 threads");
    constexpr int AS = BM + 4;
    __shared__ float As[BK][AS];
    __shared__ float Ws[BK][BN];

    int m0 = blockIdx.x * BM;
    int n0 = blockIdx.y * BN;
    int tid = threadIdx.x;
    int tx = tid % TX, ty = tid / TX;

    float acc[TM][TN];
#pragma unroll
    for (int i = 0; i < TM; i++)
#pragma unroll
        for (int j = 0; j < TN; j++) acc[i][j] = 0.0f;

    int am = tid >> 2;
    int aq = (tid & 3) * 4;

    for (int k0 = 0; k0 < K; k0 += BK) {
        {
            const float4 v = *reinterpret_cast<const float4*>(
                &A[(size_t)(m0 + am) * K + k0 + aq]);
            As[aq + 0][am] = v.x;
            As[aq + 1][am] = v.y;
            As[aq + 2][am] = v.z;
            As[aq + 3][am] = v.w;
        }
        for (int i = tid; i < BK * BN; i += 256) {
            int k = i / BN, n = i % BN;
            Ws[k][n] = W[(size_t)(k0 + k) * N + n0 + n];
        }
        __syncthreads();
#pragma unroll
        for (int kk = 0; kk < BK; kk++) {
            float a[TM], w[TN];
#pragma unroll
            for (int i = 0; i < TM; i++) a[i] = As[kk][ty * TM + i];
#pragma unroll
            for (int j = 0; j < TN; j++) w[j] = Ws[kk][tx * TN + j];
#pragma unroll
            for (int i = 0; i < TM; i++)
#pragma unroll
                for (int j = 0; j < TN; j++) acc[i][j] += a[i] * w[j];
        }
        __syncthreads();
    }
#pragma unroll
    for (int i = 0; i < TM; i++) {
        int m = m0 + ty * TM + i;
#pragma unroll
        for (int j = 0; j < TN; j++) {
            int n = n0 + tx * TN + j;
            float v = acc[i][j] + bias[n];
            if (EPI == 0) v = fmaxf(v, 0.0f);
            C[(size_t)m * N + n] = v;
        }
    }
}

// ---------------- fused wp2 -> wu1 -> wu2 -> state update (dynamic smem) -----
__global__ void __launch_bounds__(128)
fused_step(const float* __restrict__ A,           // g_bufA (h1), row len 256
           const float* __restrict__ wp2, const float* __restrict__ bp2,
           const float* __restrict__ wu1, const float* __restrict__ bu1,
           const float* __restrict__ wu2, const float* __restrict__ bu2,
           const float* __restrict__ sstep,
           float* __restrict__ state) {
    extern __shared__ float dyn[];
    float (*As)[16][68]  = reinterpret_cast<float (*)[16][68]>(dyn + FS_AS_OFF);
    float (*Ws)[16][128] = reinterpret_cast<float (*)[16][128]>(dyn + FS_WS_OFF);
    float (*Hs)[68]      = reinterpret_cast<float (*)[68]>(dyn + FS_HS_OFF);
    float* bp2s = dyn + FS_B1_OFF;
    float* bu1s = dyn + FS_B2_OFF;
    float* bu2s = dyn + FS_B3_OFF;

    int m0 = blockIdx.x * 64;
    int tid = threadIdx.x;
    int r8 = tid & 7, c16 = tid >> 3;
    int am0 = tid >> 2;
    int aq  = (tid & 3) * 4;
    int wk  = tid >> 5;
    int wn  = (tid & 31) * 4;

    if (tid < 128) { bp2s[tid] = bp2[tid]; bu1s[tid] = bu1[tid]; }
    if (tid < 16)  { bu2s[tid] = bu2[tid]; }

    float acc[8][8];
#pragma unroll
    for (int i = 0; i < 8; i++)
#pragma unroll
        for (int j = 0; j < 8; j++) acc[i][j] = 0.0f;

    // ---- phase 1: h2 = relu(h1 @ wp2 + bp2), K=256, double-buffered ----
#pragma unroll
    for (int i = 0; i < 2; i++) {
        int am = am0 + i * 32;
        float4 v = *reinterpret_cast<const float4*>(&A[(size_t)(m0 + am) * 256 + aq]);
        As[0][aq + 0][am] = v.x;
        As[0][aq + 1][am] = v.y;
        As[0][aq + 2][am] = v.z;
        As[0][aq + 3][am] = v.w;
    }
#pragma unroll
    for (int i = 0; i < 4; i++) {
        int k = wk + i * 4;
        *reinterpret_cast<float4*>(&Ws[0][k][wn]) =
            *reinterpret_cast<const float4*>(&wp2[(size_t)k * 128 + wn]);
    }
    __syncthreads();

    int p = 0;
    for (int t = 0; t < 16; t++) {
        float4 pa[2], pw[4];
        bool has = (t + 1 < 16);
        if (has) {
            int k0 = (t + 1) << 4;
#pragma unroll
            for (int i = 0; i < 2; i++)
                pa[i] = *reinterpret_cast<const float4*>(
                    &A[(size_t)(m0 + am0 + i * 32) * 256 + k0 + aq]);
#pragma unroll
            for (int i = 0; i < 4; i++)
                pw[i] = *reinterpret_cast<const float4*>(
                    &wp2[(size_t)(k0 + wk + i * 4) * 128 + wn]);
        }
#pragma unroll
        for (int kk = 0; kk < 16; kk++) {
            float4 a0 = *reinterpret_cast<const float4*>(&As[p][kk][r8 * 4]);
            float4 a1 = *reinterpret_cast<const float4*>(&As[p][kk][32 + r8 * 4]);
            float4 w0 = *reinterpret_cast<const float4*>(&Ws[p][kk][c16 * 8]);
            float4 w1 = *reinterpret_cast<const float4*>(&Ws[p][kk][c16 * 8 + 4]);
            float a[8] = {a0.x,a0.y,a0.z,a0.w,a1.x,a1.y,a1.z,a1.w};
            float w[8] = {w0.x,w0.y,w0.z,w0.w,w1.x,w1.y,w1.z,w1.w};
#pragma unroll
            for (int i = 0; i < 8; i++)
#pragma unroll
                for (int j = 0; j < 8; j++) acc[i][j] += a[i] * w[j];
        }
        if (has) {
            int q = p ^ 1;
#pragma unroll
            for (int i = 0; i < 2; i++) {
                int am = am0 + i * 32;
                As[q][aq + 0][am] = pa[i].x;
                As[q][aq + 1][am] = pa[i].y;
                As[q][aq + 2][am] = pa[i].z;
                As[q][aq + 3][am] = pa[i].w;
            }
#pragma unroll
            for (int i = 0; i < 4; i++)
                *reinterpret_cast<float4*>(&Ws[q][wk + i * 4][wn]) = pw[i];
        }
        __syncthreads();
        p ^= 1;
    }

    // epilogue 1: transposed store h2 into Hs[n][m]; preload phase-2 W tile 0
#pragma unroll
    for (int j = 0; j < 8; j++) {
        int n = c16 * 8 + j;
        float v0[4], v1[4];
#pragma unroll
        for (int i = 0; i < 4; i++) v0[i] = fmaxf(acc[i][j] + bp2s[n], 0.0f);
#pragma unroll
        for (int i = 0; i < 4; i++) v1[i] = fmaxf(acc[4 + i][j] + bp2s[n], 0.0f);
        *reinterpret_cast<float4*>(&Hs[n][r8 * 4])      = make_float4(v0[0], v0[1], v0[2], v0[3]);
        *reinterpret_cast<float4*>(&Hs[n][32 + r8 * 4]) = make_float4(v1[0], v1[1], v1[2], v1[3]);
    }
#pragma unroll
    for (int i = 0; i < 4; i++) {
        int k = wk + i * 4;
        *reinterpret_cast<float4*>(&Ws[0][k][wn]) =
            *reinterpret_cast<const float4*>(&wu1[(size_t)k * 128 + wn]);
    }
    __syncthreads();

    // ---- phase 2: dh = relu(h2 @ wu1 + bu1), K=128, A in Hs, W double-buf ----
#pragma unroll
    for (int i = 0; i < 8; i++)
#pragma unroll
        for (int j = 0; j < 8; j++) acc[i][j] = 0.0f;

    p = 0;
    for (int c = 0; c < 8; c++) {
        float4 pw[4];
        bool has = (c + 1 < 8);
        if (has) {
            int k0 = (c + 1) << 4;
#pragma unroll
            for (int i = 0; i < 4; i++)
                pw[i] = *reinterpret_cast<const float4*>(
                    &wu1[(size_t)(k0 + wk + i * 4) * 128 + wn]);
        }
#pragma unroll
        for (int kk = 0; kk < 16; kk++) {
            float4 a0 = *reinterpret_cast<const float4*>(&Hs[c * 16 + kk][r8 * 4]);
            float4 a1 = *reinterpret_cast<const float4*>(&Hs[c * 16 + kk][32 + r8 * 4]);
            float4 w0 = *reinterpret_cast<const float4*>(&Ws[p][kk][c16 * 8]);
            float4 w1 = *reinterpret_cast<const float4*>(&Ws[p][kk][c16 * 8 + 4]);
            float a[8] = {a0.x,a0.y,a0.z,a0.w,a1.x,a1.y,a1.z,a1.w};
            float w[8] = {w0.x,w0.y,w0.z,w0.w,w1.x,w1.y,w1.z,w1.w};
#pragma unroll
            for (int i = 0; i < 8; i++)
#pragma unroll
                for (int j = 0; j < 8; j++) acc[i][j] += a[i] * w[j];
        }
        if (has) {
            int q = p ^ 1;
#pragma unroll
            for (int i = 0; i < 4; i++)
                *reinterpret_cast<float4*>(&Ws[q][wk + i * 4][wn]) = pw[i];
        }
        __syncthreads();
        p ^= 1;
    }

    // epilogue 2: overwrite Hs with dh; stage wu2 into flat Ws
#pragma unroll
    for (int j = 0; j < 8; j++) {
        int n = c16 * 8 + j;
        float v0[4], v1[4];
#pragma unroll
        for (int i = 0; i < 4; i++) v0[i] = fmaxf(acc[i][j] + bu1s[n], 0.0f);
#pragma unroll
        for (int i = 0; i < 4; i++) v1[i] = fmaxf(acc[4 + i][j] + bu1s[n], 0.0f);
        *reinterpret_cast<float4*>(&Hs[n][r8 * 4])      = make_float4(v0[0], v0[1], v0[2], v0[3]);
        *reinterpret_cast<float4*>(&Hs[n][32 + r8 * 4]) = make_float4(v1[0], v1[1], v1[2], v1[3]);
    }
    {
        float* wflat = &Ws[0][0][0];
#pragma unroll
        for (int i = 0; i < 4; i++) {
            int f = (tid + i * 128) * 4;   // 2048 floats
            *reinterpret_cast<float4*>(&wflat[f]) =
                *reinterpret_cast<const float4*>(&wu2[f]);
        }
    }
    __syncthreads();

    // ---- phase 3: delta = dh @ wu2 + bu2; state += step*delta ----
    {
        const float* wflat = &Ws[0][0][0];
        int col = tid & 15;
        int rg  = tid >> 4;   // 0..7 -> rows rg*8..+7
        float acc3[8];
#pragma unroll
        for (int i = 0; i < 8; i++) acc3[i] = 0.0f;
        for (int kk = 0; kk < 128; kk++) {
            float w = wflat[kk * 16 + col];
            float4 a0 = *reinterpret_cast<const float4*>(&Hs[kk][rg * 8]);
            float4 a1 = *reinterpret_cast<const float4*>(&Hs[kk][rg * 8 + 4]);
            acc3[0] += a0.x * w; acc3[1] += a0.y * w;
            acc3[2] += a0.z * w; acc3[3] += a0.w * w;
            acc3[4] += a1.x * w; acc3[5] += a1.y * w;
            acc3[6] += a1.z * w; acc3[7] += a1.w * w;
        }
        float stp = sstep[0];
        float bv = bu2s[col];
#pragma unroll
        for (int i = 0; i < 8; i++) {
            int m = m0 + rg * 8 + i;
            state[(size_t)m * SD + col] += stp * (acc3[i] + bv);
        }
    }
}

// ---------------- initial state build ----------------------------------------
__global__ void init_state_kernel(const float* __restrict__ sx,
                                  const float* __restrict__ sy,
                                  const float* __restrict__ doff) {
    int row = blockIdx.x * blockDim.x + threadIdx.x;
    if (row >= NROWS) return;
    int n = row % NP;
    const float* ini = g_init + (size_t)row * SD;
    float* st = g_state + (size_t)row * SD;
    st[0] = sx[n] + ini[0] * 0.15f;
    st[1] = sy[n] + ini[1] * 0.15f;
    st[2] = doff[0] + g_dep[row] * -2.0f;
#pragma unroll
    for (int i = 3; i < SD; i++) st[i] = ini[i];
}

// ---------------- fused kNN + pin gather (block per batch) -------------------
__global__ void __launch_bounds__(384) neighpin_kernel() {
    __shared__ float st[NP * SD];   // 24128 B
    int b = blockIdx.x, t = threadIdx.x;

    const float4* gs = reinterpret_cast<const float4*>(g_state + (size_t)b * NP * SD);
    float4* s4 = reinterpret_cast<float4*>(st);
    for (int i = t; i < NP * SD / 4; i += 384) s4[i] = gs[i];
    __syncthreads();
    if (t >= NP) return;

    float bd[KNEI + 1];
    int bi[KNEI + 1];
#pragma unroll
    for (int i = 0; i <= KNEI; i++) { bd[i] = 3.4e38f; bi[i] = -1; }

    float x = st[t * SD + 0], y = st[t * SD + 1], z = st[t * SD + 2];
    for (int j = 0; j < NP; j++) {
        float dx = x - st[j * SD + 0];
        float dy = y - st[j * SD + 1];
        float dz = z - st[j * SD + 2];
        float d2 = dx * dx + dy * dy + dz * dz;
        if (d2 < bd[KNEI]) {
            int p = KNEI;
            while (p > 0 && bd[p - 1] > d2) {
                bd[p] = bd[p - 1];
                bi[p] = bi[p - 1];
                p--;
            }
            bd[p] = d2;
            bi[p] = j;
        }
    }

    float4* p4 = reinterpret_cast<float4*>(g_pin + (size_t)(b * NP + t) * PIN_DIM);
    const float4* self = reinterpret_cast<const float4*>(&st[t * SD]);
#pragma unroll
    for (int q = 0; q < 4; q++) p4[q] = self[q];
#pragma unroll
    for (int k = 0; k < KNEI; k++) {
        const float4* nb = reinterpret_cast<const float4*>(&st[bi[k + 1] * SD]);
#pragma unroll
        for (int q = 0; q < 4; q++) p4[4 + k * 4 + q] = nb[q];
    }
}

// ---------------- postprocess ------------------------------------------------
__device__ __forceinline__ float sgnf(float x) {
    return (x > 0.0f) ? 1.0f : ((x < 0.0f) ? -1.0f : 0.0f);
}

__global__ void final_kernel(float* __restrict__ out) {
    int row = blockIdx.x * blockDim.x + threadIdx.x;
    if (row >= NROWS) return;
    const float* s = g_state + (size_t)row * SD;
    float o[14];
    o[0] = s[0]; o[1] = s[1]; o[2] = s[2];

#pragma unroll
    for (int i = 0; i < 3; i++) {
        float tv = fminf(fmaxf(s[3 + i], -10.0f), 20.0f) + 1.0f;
        float sp = log1pf(expf(tv));
        o[3 + i] = fminf(fmaxf(sp * 0.15f, 1e-6f), 2.0f);
    }

    const float eps = 1e-8f;
    float a1x = s[6], a1y = s[7], a1z = s[8];
    float a2x = s[9], a2y = s[10], a2z = s[11];
    float n1 = sqrtf(a1x * a1x + a1y * a1y + a1z * a1z) + eps;
    float b1x = a1x / n1, b1y = a1y / n1, b1z = a1z / n1;
    float dd = b1x * a2x + b1y * a2y + b1z * a2z;
    float pxv = a2x - dd * b1x, pyv = a2y - dd * b1y, pzv = a2z - dd * b1z;
    float n2 = sqrtf(pxv * pxv + pyv * pyv + pzv * pzv) + eps;
    float b2x = pxv / n2, b2y = pyv / n2, b2z = pzv / n2;
    float b3x = b1y * b2z - b1z * b2y;
    float b3y = b1z * b2x - b1x * b2z;
    float b3z = b1x * b2y - b1y * b2x;
    float m00 = b1x, m11 = b2y, m22 = b3z;
    float qw = 0.5f * sqrtf(fmaxf(1.0f + m00 + m11 + m22, 0.0f) + eps);
    float qx = 0.5f * sqrtf(fmaxf(1.0f + m00 - m11 - m22, 0.0f) + eps) * sgnf(b2z - b3y);
    float qy = 0.5f * sqrtf(fmaxf(1.0f - m00 + m11 - m22, 0.0f) + eps) * sgnf(b3x - b1z);
    float qz = 0.5f * sqrtf(fmaxf(1.0f - m00 - m11 + m22, 0.0f) + eps) * sgnf(b1y - b2x);
    float qn = sqrtf(qw * qw + qx * qx + qy * qy + qz * qz) + eps;
    o[6] = qw / qn; o[7] = qx / qn; o[8] = qy / qn; o[9] = qz / qn;

    o[10] = 1.0f / (1.0f + expf(-s[12]));
    o[11] = 1.0f / (1.0f + expf(-s[13]));
    o[12] = 1.0f / (1.0f + expf(-s[14]));
    o[13] = 1.0f / (1.0f + expf(-s[15]));

    float* op = out + (size_t)row * 14;
#pragma unroll
    for (int i = 0; i < 14; i++) op[i] = o[i];
}

// ---------------- launch ------------------------------------------------------
extern "C" void kernel_launch(void* const* d_in, const int* in_sizes, int n_in,
                              void* d_out, int out_size) {
    const float* feat  = (const float*)d_in[0];
    const float* depth = (const float*)d_in[1];
    const float* sx    = (const float*)d_in[2];
    const float* sy    = (const float*)d_in[3];
    const float* doff  = (const float*)d_in[4];
    const float* sstep = (const float*)d_in[5];
    const float* wi1 = (const float*)d_in[6];
    const float* bi1 = (const float*)d_in[7];
    const float* wi2 = (const float*)d_in[8];
    const float* bi2 = (const float*)d_in[9];
    const float* wi3 = (const float*)d_in[10];
    const float* bi3 = (const float*)d_in[11];
    const float* wp1 = (const float*)d_in[12];
    const float* bp1 = (const float*)d_in[13];
    const float* wp2 = (const float*)d_in[14];
    const float* bp2 = (const float*)d_in[15];
    const float* wu1 = (const float*)d_in[16];
    const float* bu1 = (const float*)d_in[17];
    const float* wu2 = (const float*)d_in[18];
    const float* bu2 = (const float*)d_in[19];

    // raise dynamic smem cap for fused_step (host-side, not captured, idempotent)
    cudaFuncSetAttribute(fused_step, cudaFuncAttributeMaxDynamicSharedMemorySize,
                         FS_TOTAL_B);

    void *pFs, *pA, *pB, *pInit, *pState, *pPin;
    cudaGetSymbolAddress(&pFs, g_Fs);
    cudaGetSymbolAddress(&pA, g_bufA);
    cudaGetSymbolAddress(&pB, g_bufB);
    cudaGetSymbolAddress(&pInit, g_init);
    cudaGetSymbolAddress(&pState, g_state);
    cudaGetSymbolAddress(&pPin, g_pin);
    float* Fs = (float*)pFs;
    float* bufA = (float*)pA;
    float* bufB = (float*)pB;
    float* initb = (float*)pInit;
    float* state = (float*)pState;
    float* pin = (float*)pPin;

    const int MB = NROWS / 64;  // 377

    // launches 0,1: sampling (split so that launch #3 = workhorse GEMM for ncu)
    sample_feat_kernel<<<NROWS, 128>>>(feat, sx, sy);
    sample_depth_kernel<<<(NROWS + 127) / 128, 128>>>(depth, sx, sy);

    // launch 2: wi1 (K=384, N=256); launch 3: wi2 (K=256, N=128) <- profiled
    gemm64x128<0><<<dim3(MB, 2), 128>>>(Fs, wi1, bi1, bufA, CIN, H2X);
    gemm64x128<0><<<dim3(MB, 1), 128>>>(bufA, wi2, bi2, bufB, H2X, HID);
    gemm_kernel<64, 16, 16, 4, 1, 1><<<dim3(MB, 1), 256>>>(bufB, wi3, bi3, initb, HID, SD);

    init_state_kernel<<<(NROWS + 255) / 256, 256>>>(sx, sy, doff);

    for (int s = 0; s < NSTEPS; s++) {
        neighpin_kernel<<<BB, 384>>>();
        gemm64x128<0><<<dim3(MB, 2), 128>>>(pin, wp1, bp1, bufA, PIN_DIM, H2X);
        fused_step<<<MB, 128, FS_TOTAL_B>>>(bufA, wp2, bp2, wu1, bu1, wu2, bu2, sstep, state);
    }

    final_kernel<<<(NROWS + 255) / 256, 256>>>((float*)d_out);
}

// round 5
// speedup vs baseline: 1.3853x; 1.0345x over previous
#include <cuda_runtime.h>
#include <math.h>

// ---------------- problem constants ----------------
#define BB      64
#define NP      377
#define NROWS   (BB * NP)        // 24128 = 377 * 64
#define CIN     384
#define HID     128
#define H2X     256
#define SD      16
#define KNEI    6
#define PIN_DIM (SD * (KNEI + 1)) // 112
#define NSTEPS  16
#define FH      37
#define DHH     518

// fused_step dynamic smem layout (floats)
#define FS_AS_OFF   0                       // As[2][16][68]  = 2176
#define FS_WS_OFF   2176                    // Ws[2][16][128] = 4096
#define FS_HS_OFF   (2176 + 4096)           // Hs[128][68]    = 8704
#define FS_B1_OFF   (FS_HS_OFF + 8704)      // bp2s[128]
#define FS_B2_OFF   (FS_B1_OFF + 128)       // bu1s[128]
#define FS_B3_OFF   (FS_B2_OFF + 128)       // bu2s[16]
#define FS_TOTAL_F  (FS_B3_OFF + 16)        // 15248 floats
#define FS_TOTAL_B  (FS_TOTAL_F * 4)        // 60992 bytes

typedef unsigned long long u64;

// ---- packed f32x2 helpers (Blackwell sm_100a) -------------------------------
__device__ __forceinline__ u64 bcast2(float x) {
    u64 r;
    asm("mov.b64 %0, {%1, %1};" : "=l"(r) : "f"(x));
    return r;
}
__device__ __forceinline__ void fma2(u64& acc, u64 a, u64 w) {
    asm("fma.rn.f32x2 %0, %1, %2, %0;" : "+l"(acc) : "l"(a), "l"(w));
}
__device__ __forceinline__ void unpack2(u64 v, float& lo, float& hi) {
    asm("mov.b64 {%0, %1}, %2;" : "=f"(lo), "=f"(hi) : "l"(v));
}

// ---------------- scratch (static device memory; no allocation) -------------
__device__ float g_Fs[(size_t)NROWS * CIN];
__device__ float g_dep[NROWS];
__device__ float g_bufA[(size_t)NROWS * H2X];   // h1 (256 wide)
__device__ float g_bufB[(size_t)NROWS * HID];   // init path only
__device__ float g_init[(size_t)NROWS * SD];
__device__ float g_state[(size_t)NROWS * SD];
__device__ float g_pin[(size_t)NROWS * PIN_DIM];

// ---------------- feature bilinear sampling ----------------------------------
__global__ void sample_feat_kernel(const float* __restrict__ feat,
                                   const float* __restrict__ sx,
                                   const float* __restrict__ sy) {
    int row = blockIdx.x;
    int b = row / NP, n = row % NP;
    float gx = sx[n], gy = sy[n];

    float ix = fminf(fmaxf((gx + 1.0f) * 0.5f * (float)(FH - 1), 0.0f), (float)(FH - 1));
    float iy = fminf(fmaxf((gy + 1.0f) * 0.5f * (float)(FH - 1), 0.0f), (float)(FH - 1));
    int x0 = (int)floorf(ix), y0 = (int)floorf(iy);
    int x1 = min(x0 + 1, FH - 1), y1 = min(y0 + 1, FH - 1);
    float wx = ix - (float)x0, wy = iy - (float)y0;
    float w00 = (1.0f - wx) * (1.0f - wy);
    float w01 = wx * (1.0f - wy);
    float w10 = (1.0f - wx) * wy;
    float w11 = wx * wy;

    const float* fb = feat + (size_t)b * CIN * FH * FH;
    for (int c = threadIdx.x; c < CIN; c += blockDim.x) {
        const float* p = fb + (size_t)c * FH * FH;
        float v = p[y0 * FH + x0] * w00 + p[y0 * FH + x1] * w01 +
                  p[y1 * FH + x0] * w10 + p[y1 * FH + x1] * w11;
        g_Fs[(size_t)row * CIN + c] = v;
    }
}

// ---------------- depth bilinear sampling ------------------------------------
__global__ void sample_depth_kernel(const float* __restrict__ depth,
                                    const float* __restrict__ sx,
                                    const float* __restrict__ sy) {
    int row = blockIdx.x * blockDim.x + threadIdx.x;
    if (row >= NROWS) return;
    int b = row / NP, n = row % NP;
    float gx = sx[n], gy = sy[n];
    float jx = fminf(fmaxf((gx + 1.0f) * 0.5f * (float)(DHH - 1), 0.0f), (float)(DHH - 1));
    float jy = fminf(fmaxf((gy + 1.0f) * 0.5f * (float)(DHH - 1), 0.0f), (float)(DHH - 1));
    int a0 = (int)floorf(jx), c0 = (int)floorf(jy);
    int a1 = min(a0 + 1, DHH - 1), c1 = min(c0 + 1, DHH - 1);
    float ux = jx - (float)a0, uy = jy - (float)c0;
    const float* dp = depth + (size_t)b * DHH * DHH;
    float v = dp[c0 * DHH + a0] * (1.0f - ux) * (1.0f - uy) +
              dp[c0 * DHH + a1] * ux * (1.0f - uy) +
              dp[c1 * DHH + a0] * (1.0f - ux) * uy +
              dp[c1 * DHH + a1] * ux * uy;
    g_dep[row] = v;
}

// ---- packed 16-wide k-step micro-kernel: acc64[8][4] += a(bcast) * w(pairs) -
__device__ __forceinline__ void mma_tile16(
    u64 acc64[8][4], const float (*As)[68], const float (*Ws)[128],
    int r8, int c16) {
#pragma unroll
    for (int kk = 0; kk < 16; kk++) {
        float4 a0 = *reinterpret_cast<const float4*>(&As[kk][r8 * 4]);
        float4 a1 = *reinterpret_cast<const float4*>(&As[kk][32 + r8 * 4]);
        ulonglong2 wva = *reinterpret_cast<const ulonglong2*>(&Ws[kk][c16 * 8]);
        ulonglong2 wvb = *reinterpret_cast<const ulonglong2*>(&Ws[kk][c16 * 8 + 4]);
        u64 wpk[4] = {wva.x, wva.y, wvb.x, wvb.y};
        u64 ab[8] = {bcast2(a0.x), bcast2(a0.y), bcast2(a0.z), bcast2(a0.w),
                     bcast2(a1.x), bcast2(a1.y), bcast2(a1.z), bcast2(a1.w)};
#pragma unroll
        for (int i = 0; i < 8; i++)
#pragma unroll
            for (int j = 0; j < 4; j++) fma2(acc64[i][j], ab[i], wpk[j]);
    }
}

// ---------------- 64x128 GEMM, 128 threads, 8x8 microtile, double-buffered ---
// f32x2 packed accumulation (bitwise identical to scalar FFMA).
template <int EPI>
__global__ void __launch_bounds__(128)
gemm64x128(const float* __restrict__ A, const float* __restrict__ W,
           const float* __restrict__ bias, float* __restrict__ C,
           int K, int N) {
    __shared__ float As[2][16][68];
    __shared__ float Ws[2][16][128];

    int m0 = blockIdx.x * 64;
    int n0 = blockIdx.y * 128;
    int tid = threadIdx.x;
    int r8 = tid & 7, c16 = tid >> 3;

    int am0 = tid >> 2;            // 0..31; second A row group at +32
    int aq  = (tid & 3) * 4;       // 0,4,8,12
    int wk  = tid >> 5;            // 0..3
    int wn  = (tid & 31) * 4;

    u64 acc64[8][4];
#pragma unroll
    for (int i = 0; i < 8; i++)
#pragma unroll
        for (int j = 0; j < 4; j++) acc64[i][j] = 0ull;

    // preload tile 0
#pragma unroll
    for (int i = 0; i < 2; i++) {
        int am = am0 + i * 32;
        float4 v = *reinterpret_cast<const float4*>(&A[(size_t)(m0 + am) * K + aq]);
        As[0][aq + 0][am] = v.x;
        As[0][aq + 1][am] = v.y;
        As[0][aq + 2][am] = v.z;
        As[0][aq + 3][am] = v.w;
    }
#pragma unroll
    for (int i = 0; i < 4; i++) {
        int k = wk + i * 4;
        *reinterpret_cast<float4*>(&Ws[0][k][wn]) =
            *reinterpret_cast<const float4*>(&W[(size_t)k * N + n0 + wn]);
    }
    __syncthreads();

    int KT = K >> 4;
    int p = 0;
    for (int t = 0; t < KT; t++) {
        float4 pa[2], pw[4];
        bool has = (t + 1 < KT);
        if (has) {
            int k0 = (t + 1) << 4;
#pragma unroll
            for (int i = 0; i < 2; i++)
                pa[i] = *reinterpret_cast<const float4*>(
                    &A[(size_t)(m0 + am0 + i * 32) * K + k0 + aq]);
#pragma unroll
            for (int i = 0; i < 4; i++)
                pw[i] = *reinterpret_cast<const float4*>(
                    &W[(size_t)(k0 + wk + i * 4) * N + n0 + wn]);
        }

        mma_tile16(acc64, As[p], Ws[p], r8, c16);

        if (has) {
            int q = p ^ 1;
#pragma unroll
            for (int i = 0; i < 2; i++) {
                int am = am0 + i * 32;
                As[q][aq + 0][am] = pa[i].x;
                As[q][aq + 1][am] = pa[i].y;
                As[q][aq + 2][am] = pa[i].z;
                As[q][aq + 3][am] = pa[i].w;
            }
#pragma unroll
            for (int i = 0; i < 4; i++)
                *reinterpret_cast<float4*>(&Ws[q][wk + i * 4][wn]) = pw[i];
        }
        __syncthreads();
        p ^= 1;
    }

    float acc[8][8];
#pragma unroll
    for (int i = 0; i < 8; i++)
#pragma unroll
        for (int j = 0; j < 4; j++) unpack2(acc64[i][j], acc[i][2 * j], acc[i][2 * j + 1]);

    float bb[8];
#pragma unroll
    for (int j = 0; j < 8; j++) bb[j] = bias[n0 + c16 * 8 + j];
#pragma unroll
    for (int h = 0; h < 2; h++) {
#pragma unroll
        for (int i = 0; i < 4; i++) {
            int m = m0 + h * 32 + r8 * 4 + i;
            int ai = h * 4 + i;
            float v[8];
#pragma unroll
            for (int j = 0; j < 8; j++) {
                v[j] = acc[ai][j] + bb[j];
                if (EPI == 0) v[j] = fmaxf(v[j], 0.0f);
            }
            float4* cp = reinterpret_cast<float4*>(&C[(size_t)m * N + n0 + c16 * 8]);
            cp[0] = make_float4(v[0], v[1], v[2], v[3]);
            cp[1] = make_float4(v[4], v[5], v[6], v[7]);
        }
    }
}

// ---------------- small GEMM (N=16), used once for wi3 -----------------------
template <int BM, int BN, int BK, int TM, int TN, int EPI>
__global__ void gemm_kernel(const float* __restrict__ A,
                            const float* __restrict__ W,
                            const float* __restrict__ bias,
                            float* __restrict__ C,
                            int K, int N) {
    constexpr int TX = BN / TN;
    constexpr int TY = BM / TM;
    static_assert(TX * TY == 256, "256 threads");
    constexpr int AS = BM + 4;
    __shared__ float As[BK][AS];
    __shared__ float Ws[BK][BN];

    int m0 = blockIdx.x * BM;
    int n0 = blockIdx.y * BN;
    int tid = threadIdx.x;
    int tx = tid % TX, ty = tid / TX;

    float acc[TM][TN];
#pragma unroll
    for (int i = 0; i < TM; i++)
#pragma unroll
        for (int j = 0; j < TN; j++) acc[i][j] = 0.0f;

    int am = tid >> 2;
    int aq = (tid & 3) * 4;

    for (int k0 = 0; k0 < K; k0 += BK) {
        {
            const float4 v = *reinterpret_cast<const float4*>(
                &A[(size_t)(m0 + am) * K + k0 + aq]);
            As[aq + 0][am] = v.x;
            As[aq + 1][am] = v.y;
            As[aq + 2][am] = v.z;
            As[aq + 3][am] = v.w;
        }
        for (int i = tid; i < BK * BN; i += 256) {
            int k = i / BN, n = i % BN;
            Ws[k][n] = W[(size_t)(k0 + k) * N + n0 + n];
        }
        __syncthreads();
#pragma unroll
        for (int kk = 0; kk < BK; kk++) {
            float a[TM], w[TN];
#pragma unroll
            for (int i = 0; i < TM; i++) a[i] = As[kk][ty * TM + i];
#pragma unroll
            for (int j = 0; j < TN; j++) w[j] = Ws[kk][tx * TN + j];
#pragma unroll
            for (int i = 0; i < TM; i++)
#pragma unroll
                for (int j = 0; j < TN; j++) acc[i][j] += a[i] * w[j];
        }
        __syncthreads();
    }
#pragma unroll
    for (int i = 0; i < TM; i++) {
        int m = m0 + ty * TM + i;
#pragma unroll
        for (int j = 0; j < TN; j++) {
            int n = n0 + tx * TN + j;
            float v = acc[i][j] + bias[n];
            if (EPI == 0) v = fmaxf(v, 0.0f);
            C[(size_t)m * N + n] = v;
        }
    }
}

// ---------------- fused wp2 -> wu1 -> wu2 -> state update (dynamic smem) -----
__global__ void __launch_bounds__(128)
fused_step(const float* __restrict__ A,           // g_bufA (h1), row len 256
           const float* __restrict__ wp2, const float* __restrict__ bp2,
           const float* __restrict__ wu1, const float* __restrict__ bu1,
           const float* __restrict__ wu2, const float* __restrict__ bu2,
           const float* __restrict__ sstep,
           float* __restrict__ state) {
    extern __shared__ float dyn[];
    float (*As)[16][68]  = reinterpret_cast<float (*)[16][68]>(dyn + FS_AS_OFF);
    float (*Ws)[16][128] = reinterpret_cast<float (*)[16][128]>(dyn + FS_WS_OFF);
    float (*Hs)[68]      = reinterpret_cast<float (*)[68]>(dyn + FS_HS_OFF);
    float* bp2s = dyn + FS_B1_OFF;
    float* bu1s = dyn + FS_B2_OFF;
    float* bu2s = dyn + FS_B3_OFF;

    int m0 = blockIdx.x * 64;
    int tid = threadIdx.x;
    int r8 = tid & 7, c16 = tid >> 3;
    int am0 = tid >> 2;
    int aq  = (tid & 3) * 4;
    int wk  = tid >> 5;
    int wn  = (tid & 31) * 4;

    if (tid < 128) { bp2s[tid] = bp2[tid]; bu1s[tid] = bu1[tid]; }
    if (tid < 16)  { bu2s[tid] = bu2[tid]; }

    u64 acc64[8][4];
#pragma unroll
    for (int i = 0; i < 8; i++)
#pragma unroll
        for (int j = 0; j < 4; j++) acc64[i][j] = 0ull;

    // ---- phase 1: h2 = relu(h1 @ wp2 + bp2), K=256, double-buffered ----
#pragma unroll
    for (int i = 0; i < 2; i++) {
        int am = am0 + i * 32;
        float4 v = *reinterpret_cast<const float4*>(&A[(size_t)(m0 + am) * 256 + aq]);
        As[0][aq + 0][am] = v.x;
        As[0][aq + 1][am] = v.y;
        As[0][aq + 2][am] = v.z;
        As[0][aq + 3][am] = v.w;
    }
#pragma unroll
    for (int i = 0; i < 4; i++) {
        int k = wk + i * 4;
        *reinterpret_cast<float4*>(&Ws[0][k][wn]) =
            *reinterpret_cast<const float4*>(&wp2[(size_t)k * 128 + wn]);
    }
    __syncthreads();

    int p = 0;
    for (int t = 0; t < 16; t++) {
        float4 pa[2], pw[4];
        bool has = (t + 1 < 16);
        if (has) {
            int k0 = (t + 1) << 4;
#pragma unroll
            for (int i = 0; i < 2; i++)
                pa[i] = *reinterpret_cast<const float4*>(
                    &A[(size_t)(m0 + am0 + i * 32) * 256 + k0 + aq]);
#pragma unroll
            for (int i = 0; i < 4; i++)
                pw[i] = *reinterpret_cast<const float4*>(
                    &wp2[(size_t)(k0 + wk + i * 4) * 128 + wn]);
        }
        mma_tile16(acc64, As[p], Ws[p], r8, c16);
        if (has) {
            int q = p ^ 1;
#pragma unroll
            for (int i = 0; i < 2; i++) {
                int am = am0 + i * 32;
                As[q][aq + 0][am] = pa[i].x;
                As[q][aq + 1][am] = pa[i].y;
                As[q][aq + 2][am] = pa[i].z;
                As[q][aq + 3][am] = pa[i].w;
            }
#pragma unroll
            for (int i = 0; i < 4; i++)
                *reinterpret_cast<float4*>(&Ws[q][wk + i * 4][wn]) = pw[i];
        }
        __syncthreads();
        p ^= 1;
    }

    // epilogue 1: transposed store h2 into Hs[n][m]; preload phase-2 W tile 0
    {
        float acc[8][8];
#pragma unroll
        for (int i = 0; i < 8; i++)
#pragma unroll
            for (int j = 0; j < 4; j++) unpack2(acc64[i][j], acc[i][2 * j], acc[i][2 * j + 1]);
#pragma unroll
        for (int j = 0; j < 8; j++) {
            int n = c16 * 8 + j;
            float v0[4], v1[4];
#pragma unroll
            for (int i = 0; i < 4; i++) v0[i] = fmaxf(acc[i][j] + bp2s[n], 0.0f);
#pragma unroll
            for (int i = 0; i < 4; i++) v1[i] = fmaxf(acc[4 + i][j] + bp2s[n], 0.0f);
            *reinterpret_cast<float4*>(&Hs[n][r8 * 4])      = make_float4(v0[0], v0[1], v0[2], v0[3]);
            *reinterpret_cast<float4*>(&Hs[n][32 + r8 * 4]) = make_float4(v1[0], v1[1], v1[2], v1[3]);
        }
    }
#pragma unroll
    for (int i = 0; i < 4; i++) {
        int k = wk + i * 4;
        *reinterpret_cast<float4*>(&Ws[0][k][wn]) =
            *reinterpret_cast<const float4*>(&wu1[(size_t)k * 128 + wn]);
    }
    __syncthreads();

    // ---- phase 2: dh = relu(h2 @ wu1 + bu1), K=128, A in Hs, W double-buf ----
#pragma unroll
    for (int i = 0; i < 8; i++)
#pragma unroll
        for (int j = 0; j < 4; j++) acc64[i][j] = 0ull;

    p = 0;
    for (int c = 0; c < 8; c++) {
        float4 pw[4];
        bool has = (c + 1 < 8);
        if (has) {
            int k0 = (c + 1) << 4;
#pragma unroll
            for (int i = 0; i < 4; i++)
                pw[i] = *reinterpret_cast<const float4*>(
                    &wu1[(size_t)(k0 + wk + i * 4) * 128 + wn]);
        }
        mma_tile16(acc64, reinterpret_cast<const float (*)[68]>(Hs[c * 16]), Ws[p], r8, c16);
        if (has) {
            int q = p ^ 1;
#pragma unroll
            for (int i = 0; i < 4; i++)
                *reinterpret_cast<float4*>(&Ws[q][wk + i * 4][wn]) = pw[i];
        }
        __syncthreads();
        p ^= 1;
    }

    // epilogue 2: overwrite Hs with dh; stage wu2 into flat Ws
    {
        float acc[8][8];
#pragma unroll
        for (int i = 0; i < 8; i++)
#pragma unroll
            for (int j = 0; j < 4; j++) unpack2(acc64[i][j], acc[i][2 * j], acc[i][2 * j + 1]);
#pragma unroll
        for (int j = 0; j < 8; j++) {
            int n = c16 * 8 + j;
            float v0[4], v1[4];
#pragma unroll
            for (int i = 0; i < 4; i++) v0[i] = fmaxf(acc[i][j] + bu1s[n], 0.0f);
#pragma unroll
            for (int i = 0; i < 4; i++) v1[i] = fmaxf(acc[4 + i][j] + bu1s[n], 0.0f);
            *reinterpret_cast<float4*>(&Hs[n][r8 * 4])      = make_float4(v0[0], v0[1], v0[2], v0[3]);
            *reinterpret_cast<float4*>(&Hs[n][32 + r8 * 4]) = make_float4(v1[0], v1[1], v1[2], v1[3]);
        }
    }
    {
        float* wflat = &Ws[0][0][0];
#pragma unroll
        for (int i = 0; i < 4; i++) {
            int f = (tid + i * 128) * 4;   // 2048 floats
            *reinterpret_cast<float4*>(&wflat[f]) =
                *reinterpret_cast<const float4*>(&wu2[f]);
        }
    }
    __syncthreads();

    // ---- phase 3: delta = dh @ wu2 + bu2; state += step*delta ----
    {
        const float* wflat = &Ws[0][0][0];
        int col = tid & 15;
        int rg  = tid >> 4;   // 0..7 -> rows rg*8..+7
        float acc3[8];
#pragma unroll
        for (int i = 0; i < 8; i++) acc3[i] = 0.0f;
        for (int kk = 0; kk < 128; kk++) {
            float w = wflat[kk * 16 + col];
            float4 a0 = *reinterpret_cast<const float4*>(&Hs[kk][rg * 8]);
            float4 a1 = *reinterpret_cast<const float4*>(&Hs[kk][rg * 8 + 4]);
            acc3[0] += a0.x * w; acc3[1] += a0.y * w;
            acc3[2] += a0.z * w; acc3[3] += a0.w * w;
            acc3[4] += a1.x * w; acc3[5] += a1.y * w;
            acc3[6] += a1.z * w; acc3[7] += a1.w * w;
        }
        float stp = sstep[0];
        float bv = bu2s[col];
#pragma unroll
        for (int i = 0; i < 8; i++) {
            int m = m0 + rg * 8 + i;
            state[(size_t)m * SD + col] += stp * (acc3[i] + bv);
        }
    }
}

// ---------------- initial state build ----------------------------------------
__global__ void init_state_kernel(const float* __restrict__ sx,
                                  const float* __restrict__ sy,
                                  const float* __restrict__ doff) {
    int row = blockIdx.x * blockDim.x + threadIdx.x;
    if (row >= NROWS) return;
    int n = row % NP;
    const float* ini = g_init + (size_t)row * SD;
    float* st = g_state + (size_t)row * SD;
    st[0] = sx[n] + ini[0] * 0.15f;
    st[1] = sy[n] + ini[1] * 0.15f;
    st[2] = doff[0] + g_dep[row] * -2.0f;
#pragma unroll
    for (int i = 3; i < SD; i++) st[i] = ini[i];
}

// ---------------- fused kNN + pin gather (block per batch) -------------------
__global__ void __launch_bounds__(384) neighpin_kernel() {
    __shared__ float st[NP * SD];   // 24128 B
    int b = blockIdx.x, t = threadIdx.x;

    const float4* gs = reinterpret_cast<const float4*>(g_state + (size_t)b * NP * SD);
    float4* s4 = reinterpret_cast<float4*>(st);
    for (int i = t; i < NP * SD / 4; i += 384) s4[i] = gs[i];
    __syncthreads();
    if (t >= NP) return;

    float bd[KNEI + 1];
    int bi[KNEI + 1];
#pragma unroll
    for (int i = 0; i <= KNEI; i++) { bd[i] = 3.4e38f; bi[i] = -1; }

    float x = st[t * SD + 0], y = st[t * SD + 1], z = st[t * SD + 2];
    for (int j = 0; j < NP; j++) {
        float dx = x - st[j * SD + 0];
        float dy = y - st[j * SD + 1];
        float dz = z - st[j * SD + 2];
        float d2 = dx * dx + dy * dy + dz * dz;
        if (d2 < bd[KNEI]) {
            int p = KNEI;
            while (p > 0 && bd[p - 1] > d2) {
                bd[p] = bd[p - 1];
                bi[p] = bi[p - 1];
                p--;
            }
            bd[p] = d2;
            bi[p] = j;
        }
    }

    float4* p4 = reinterpret_cast<float4*>(g_pin + (size_t)(b * NP + t) * PIN_DIM);
    const float4* self = reinterpret_cast<const float4*>(&st[t * SD]);
#pragma unroll
    for (int q = 0; q < 4; q++) p4[q] = self[q];
#pragma unroll
    for (int k = 0; k < KNEI; k++) {
        const float4* nb = reinterpret_cast<const float4*>(&st[bi[k + 1] * SD]);
#pragma unroll
        for (int q = 0; q < 4; q++) p4[4 + k * 4 + q] = nb[q];
    }
}

// ---------------- postprocess ------------------------------------------------
__device__ __forceinline__ float sgnf(float x) {
    return (x > 0.0f) ? 1.0f : ((x < 0.0f) ? -1.0f : 0.0f);
}

__global__ void final_kernel(float* __restrict__ out) {
    int row = blockIdx.x * blockDim.x + threadIdx.x;
    if (row >= NROWS) return;
    const float* s = g_state + (size_t)row * SD;
    float o[14];
    o[0] = s[0]; o[1] = s[1]; o[2] = s[2];

#pragma unroll
    for (int i = 0; i < 3; i++) {
        float tv = fminf(fmaxf(s[3 + i], -10.0f), 20.0f) + 1.0f;
        float sp = log1pf(expf(tv));
        o[3 + i] = fminf(fmaxf(sp * 0.15f, 1e-6f), 2.0f);
    }

    const float eps = 1e-8f;
    float a1x = s[6], a1y = s[7], a1z = s[8];
    float a2x = s[9], a2y = s[10], a2z = s[11];
    float n1 = sqrtf(a1x * a1x + a1y * a1y + a1z * a1z) + eps;
    float b1x = a1x / n1, b1y = a1y / n1, b1z = a1z / n1;
    float dd = b1x * a2x + b1y * a2y + b1z * a2z;
    float pxv = a2x - dd * b1x, pyv = a2y - dd * b1y, pzv = a2z - dd * b1z;
    float n2 = sqrtf(pxv * pxv + pyv * pyv + pzv * pzv) + eps;
    float b2x = pxv / n2, b2y = pyv / n2, b2z = pzv / n2;
    float b3x = b1y * b2z - b1z * b2y;
    float b3y = b1z * b2x - b1x * b2z;
    float b3z = b1x * b2y - b1y * b2x;
    float m00 = b1x, m11 = b2y, m22 = b3z;
    float qw = 0.5f * sqrtf(fmaxf(1.0f + m00 + m11 + m22, 0.0f) + eps);
    float qx = 0.5f * sqrtf(fmaxf(1.0f + m00 - m11 - m22, 0.0f) + eps) * sgnf(b2z - b3y);
    float qy = 0.5f * sqrtf(fmaxf(1.0f - m00 + m11 - m22, 0.0f) + eps) * sgnf(b3x - b1z);
    float qz = 0.5f * sqrtf(fmaxf(1.0f - m00 - m11 + m22, 0.0f) + eps) * sgnf(b1y - b2x);
    float qn = sqrtf(qw * qw + qx * qx + qy * qy + qz * qz) + eps;
    o[6] = qw / qn; o[7] = qx / qn; o[8] = qy / qn; o[9] = qz / qn;

    o[10] = 1.0f / (1.0f + expf(-s[12]));
    o[11] = 1.0f / (1.0f + expf(-s[13]));
    o[12] = 1.0f / (1.0f + expf(-s[14]));
    o[13] = 1.0f / (1.0f + expf(-s[15]));

    float* op = out + (size_t)row * 14;
#pragma unroll
    for (int i = 0; i < 14; i++) op[i] = o[i];
}

// ---------------- launch ------------------------------------------------------
extern "C" void kernel_launch(void* const* d_in, const int* in_sizes, int n_in,
                              void* d_out, int out_size) {
    const float* feat  = (const float*)d_in[0];
    const float* depth = (const float*)d_in[1];
    const float* sx    = (const float*)d_in[2];
    const float* sy    = (const float*)d_in[3];
    const float* doff  = (const float*)d_in[4];
    const float* sstep = (const float*)d_in[5];
    const float* wi1 = (const float*)d_in[6];
    const float* bi1 = (const float*)d_in[7];
    const float* wi2 = (const float*)d_in[8];
    const float* bi2 = (const float*)d_in[9];
    const float* wi3 = (const float*)d_in[10];
    const float* bi3 = (const float*)d_in[11];
    const float* wp1 = (const float*)d_in[12];
    const float* bp1 = (const float*)d_in[13];
    const float* wp2 = (const float*)d_in[14];
    const float* bp2 = (const float*)d_in[15];
    const float* wu1 = (const float*)d_in[16];
    const float* bu1 = (const float*)d_in[17];
    const float* wu2 = (const float*)d_in[18];
    const float* bu2 = (const float*)d_in[19];

    cudaFuncSetAttribute(fused_step, cudaFuncAttributeMaxDynamicSharedMemorySize,
                         FS_TOTAL_B);

    void *pFs, *pA, *pB, *pInit, *pState, *pPin;
    cudaGetSymbolAddress(&pFs, g_Fs);
    cudaGetSymbolAddress(&pA, g_bufA);
    cudaGetSymbolAddress(&pB, g_bufB);
    cudaGetSymbolAddress(&pInit, g_init);
    cudaGetSymbolAddress(&pState, g_state);
    cudaGetSymbolAddress(&pPin, g_pin);
    float* Fs = (float*)pFs;
    float* bufA = (float*)pA;
    float* bufB = (float*)pB;
    float* initb = (float*)pInit;
    float* state = (float*)pState;
    float* pin = (float*)pPin;

    const int MB = NROWS / 64;  // 377

    // launches 0,1: sampling (split so that launch #3 = workhorse GEMM for ncu)
    sample_feat_kernel<<<NROWS, 128>>>(feat, sx, sy);
    sample_depth_kernel<<<(NROWS + 127) / 128, 128>>>(depth, sx, sy);

    // launch 2: wi1 (K=384, N=256); launch 3: wi2 (K=256, N=128) <- profiled
    gemm64x128<0><<<dim3(MB, 2), 128>>>(Fs, wi1, bi1, bufA, CIN, H2X);
    gemm64x128<0><<<dim3(MB, 1), 128>>>(bufA, wi2, bi2, bufB, H2X, HID);
    gemm_kernel<64, 16, 16, 4, 1, 1><<<dim3(MB, 1), 256>>>(bufB, wi3, bi3, initb, HID, SD);

    init_state_kernel<<<(NROWS + 255) / 256, 256>>>(sx, sy, doff);

    for (int s = 0; s < NSTEPS; s++) {
        neighpin_kernel<<<BB, 384>>>();
        gemm64x128<0><<<dim3(MB, 2), 128>>>(pin, wp1, bp1, bufA, PIN_DIM, H2X);
        fused_step<<<MB, 128, FS_TOTAL_B>>>(bufA, wp2, bp2, wu1, bu1, wu2, bu2, sstep, state);
    }

    final_kernel<<<(NROWS + 255) / 256, 256>>>((float*)d_out);
}